// round 1
// baseline (speedup 1.0000x reference)
#include <cuda_runtime.h>
#include <math.h>

#define BATCH 2
#define NSEQ  2048
#define DMODEL 2048
#define HEADS 16
#define DHEAD 128
#define ROWS (BATCH*NSEQ)   // 4096

// scratch (device globals: no allocation allowed)
__device__ float g_q[ROWS*DMODEL];
__device__ float g_k[ROWS*DMODEL];
__device__ float g_v[ROWS*DMODEL];
__device__ float g_att[ROWS*DMODEL];

// ---------------------------------------------------------------------------
// SGEMM: C[M,N] = A[M,K] @ W[K,N] + bias[N]
// M=4096, K=2048, N=2048 fixed. 128x128 tile, BK=8, 256 threads, 8x8 microtile
// ---------------------------------------------------------------------------
__global__ __launch_bounds__(256)
void sgemm_bias(const float* __restrict__ A, const float* __restrict__ W,
                const float* __restrict__ bias, float* __restrict__ C)
{
    const int K = DMODEL, Nn = DMODEL;
    __shared__ float As[8][128];
    __shared__ float Bs[8][128];

    int tid  = threadIdx.x;
    int brow = blockIdx.y * 128;
    int bcol = blockIdx.x * 128;
    int ty = tid >> 4, tx = tid & 15;

    float acc[8][8];
#pragma unroll
    for (int i = 0; i < 8; i++)
#pragma unroll
        for (int j = 0; j < 8; j++) acc[i][j] = 0.f;

    int a_r  = tid >> 1;          // 0..127
    int a_c4 = (tid & 1) << 2;    // 0 or 4
    int b_r  = tid >> 5;          // 0..7
    int b_c4 = (tid & 31) << 2;   // 0..124

    for (int k0 = 0; k0 < K; k0 += 8) {
        float4 av = *(const float4*)&A[(size_t)(brow + a_r) * K + k0 + a_c4];
        As[a_c4 + 0][a_r] = av.x;
        As[a_c4 + 1][a_r] = av.y;
        As[a_c4 + 2][a_r] = av.z;
        As[a_c4 + 3][a_r] = av.w;
        *(float4*)&Bs[b_r][b_c4] = *(const float4*)&W[(size_t)(k0 + b_r) * Nn + bcol + b_c4];
        __syncthreads();

#pragma unroll
        for (int kk = 0; kk < 8; kk++) {
            float a[8], b[8];
#pragma unroll
            for (int i = 0; i < 8; i++) a[i] = As[kk][ty * 8 + i];
#pragma unroll
            for (int j = 0; j < 8; j++) b[j] = Bs[kk][tx * 8 + j];
#pragma unroll
            for (int i = 0; i < 8; i++)
#pragma unroll
                for (int j = 0; j < 8; j++)
                    acc[i][j] += a[i] * b[j];
        }
        __syncthreads();
    }

#pragma unroll
    for (int i = 0; i < 8; i++) {
        int r = brow + ty * 8 + i;
#pragma unroll
        for (int j = 0; j < 8; j += 4) {
            int c = bcol + tx * 8 + j;
            float4 o;
            o.x = acc[i][j + 0] + bias[c + 0];
            o.y = acc[i][j + 1] + bias[c + 1];
            o.z = acc[i][j + 2] + bias[c + 2];
            o.w = acc[i][j + 3] + bias[c + 3];
            *(float4*)&C[(size_t)r * Nn + c] = o;
        }
    }
}

// ---------------------------------------------------------------------------
// Rotary: in-place on q (with scale) and k. Each thread handles the pair
// (d, d+64) within a head — same angle for both halves (pos = cat(freqs,freqs)).
// ---------------------------------------------------------------------------
__global__ __launch_bounds__(256)
void rotary_kernel(float* __restrict__ q, float* __restrict__ k)
{
    int idx = blockIdx.x * blockDim.x + threadIdx.x;   // over ROWS*HEADS*64 pairs
    const int PAIRS = ROWS * HEADS * 64;
    if (idx >= PAIRS) return;

    int row = idx / (HEADS * 64);
    int rem = idx % (HEADS * 64);
    int h = rem >> 6;
    int d = rem & 63;
    int n = row % NSEQ;

    // inv_freq = 10000^(-(2d)/128)
    float inv_freq = __expf(-((float)(2 * d) / 128.0f) * 9.210340371976184f);
    float ang = (float)n * inv_freq;
    float s, c;
    sincosf(ang, &s, &c);

    size_t base = (size_t)row * DMODEL + h * DHEAD + d;
    const float scale = 0.08838834764831845f;  // 128^-0.5

    float q1 = q[base], q2 = q[base + 64];
    q[base]      = (q1 * c - q2 * s) * scale;
    q[base + 64] = (q2 * c + q1 * s) * scale;

    float k1 = k[base], k2 = k[base + 64];
    k[base]      = k1 * c - k2 * s;
    k[base + 64] = k2 * c + k1 * s;
}

// ---------------------------------------------------------------------------
// Flash attention (causal), fp32. Br = Bc = 64, 256 threads.
// q/k/v layout: [b*n, 2048], head h at column offset h*128.
// ---------------------------------------------------------------------------
#define BR 64
#define BC 64
#define QK_PAD 132   // row stride for Q/K/V tiles (keeps float4 alignment, kills conflicts)
#define S_PAD  68

#define FLASH_SMEM ((3 * BR * QK_PAD + BR * S_PAD + 3 * BR) * 4)

__global__ __launch_bounds__(256)
void flash_attn(const float* __restrict__ q, const float* __restrict__ k,
                const float* __restrict__ v, float* __restrict__ o)
{
    extern __shared__ float sm[];
    float* Qs   = sm;                      // [64][132]
    float* Ks   = Qs + BR * QK_PAD;        // [64][132]
    float* Vs   = Ks + BR * QK_PAD;        // [64][132]
    float* Ss   = Vs + BR * QK_PAD;        // [64][68]
    float* mrow = Ss + BR * S_PAD;         // [64]
    float* lrow = mrow + BR;               // [64]
    float* fac  = lrow + BR;               // [64]

    int tid = threadIdx.x;
    int it  = blockIdx.x;                  // q-tile index
    int bh  = blockIdx.y;
    int b = bh >> 4, h = bh & 15;

    const float* qb = q + (size_t)b * NSEQ * DMODEL + h * DHEAD;
    const float* kb = k + (size_t)b * NSEQ * DMODEL + h * DHEAD;
    const float* vb = v + (size_t)b * NSEQ * DMODEL + h * DHEAD;
    float*       ob = o + (size_t)b * NSEQ * DMODEL + h * DHEAD;

    int i0 = it * BR;

    // load Q tile
    for (int x = tid; x < BR * 32; x += 256) {
        int r = x >> 5, c4 = (x & 31) << 2;
        *(float4*)&Qs[r * QK_PAD + c4] = *(const float4*)&qb[(size_t)(i0 + r) * DMODEL + c4];
    }
    if (tid < BR) { mrow[tid] = -INFINITY; lrow[tid] = 0.f; }

    float oacc[4][8];
#pragma unroll
    for (int i = 0; i < 4; i++)
#pragma unroll
        for (int j = 0; j < 8; j++) oacc[i][j] = 0.f;

    int ty = tid >> 4, tx = tid & 15;
    __syncthreads();

    for (int jt = 0; jt <= it; jt++) {
        int j0 = jt * BC;
        // load K, V tiles
        for (int x = tid; x < BC * 32; x += 256) {
            int r = x >> 5, c4 = (x & 31) << 2;
            *(float4*)&Ks[r * QK_PAD + c4] = *(const float4*)&kb[(size_t)(j0 + r) * DMODEL + c4];
            *(float4*)&Vs[r * QK_PAD + c4] = *(const float4*)&vb[(size_t)(j0 + r) * DMODEL + c4];
        }
        __syncthreads();

        // S = Q @ K^T   (each thread: 4x4 microtile)
        float s4[4][4];
#pragma unroll
        for (int i = 0; i < 4; i++)
#pragma unroll
            for (int j = 0; j < 4; j++) s4[i][j] = 0.f;

        for (int d = 0; d < DHEAD; d++) {
            float a[4], bb[4];
#pragma unroll
            for (int i = 0; i < 4; i++) a[i]  = Qs[(ty * 4 + i) * QK_PAD + d];
#pragma unroll
            for (int j = 0; j < 4; j++) bb[j] = Ks[(tx * 4 + j) * QK_PAD + d];
#pragma unroll
            for (int i = 0; i < 4; i++)
#pragma unroll
                for (int j = 0; j < 4; j++)
                    s4[i][j] += a[i] * bb[j];
        }

        if (jt == it) {
#pragma unroll
            for (int i = 0; i < 4; i++)
#pragma unroll
                for (int j = 0; j < 4; j++)
                    if (j0 + tx * 4 + j > i0 + ty * 4 + i) s4[i][j] = -INFINITY;
        }

#pragma unroll
        for (int i = 0; i < 4; i++)
#pragma unroll
            for (int j = 0; j < 4; j++)
                Ss[(ty * 4 + i) * S_PAD + tx * 4 + j] = s4[i][j];
        __syncthreads();

        // online softmax per row (threads 0..63)
        if (tid < BR) {
            float m_old = mrow[tid];
            float mx = m_old;
            for (int j = 0; j < BC; j++) mx = fmaxf(mx, Ss[tid * S_PAD + j]);
            float f = __expf(m_old - mx);    // exp(-inf)=0 on first tile
            float sum = 0.f;
            for (int j = 0; j < BC; j++) {
                float p = __expf(Ss[tid * S_PAD + j] - mx);
                Ss[tid * S_PAD + j] = p;
                sum += p;
            }
            mrow[tid] = mx;
            lrow[tid] = lrow[tid] * f + sum;
            fac[tid]  = f;
        }
        __syncthreads();

        // O = O*fac + P @ V   (each thread: 4 rows x 8 cols)
#pragma unroll
        for (int i = 0; i < 4; i++) {
            float f = fac[ty * 4 + i];
#pragma unroll
            for (int j = 0; j < 8; j++) oacc[i][j] *= f;
        }
        for (int jj = 0; jj < BC; jj++) {
            float p[4], vv[8];
#pragma unroll
            for (int i = 0; i < 4; i++) p[i] = Ss[(ty * 4 + i) * S_PAD + jj];
#pragma unroll
            for (int j = 0; j < 8; j++) vv[j] = Vs[jj * QK_PAD + tx * 8 + j];
#pragma unroll
            for (int i = 0; i < 4; i++)
#pragma unroll
                for (int j = 0; j < 8; j++)
                    oacc[i][j] += p[i] * vv[j];
        }
        __syncthreads();
    }

    // epilogue: divide by l, store
#pragma unroll
    for (int i = 0; i < 4; i++) {
        float inv = 1.0f / lrow[ty * 4 + i];
        int r = i0 + ty * 4 + i;
#pragma unroll
        for (int j = 0; j < 8; j += 4) {
            float4 ov;
            ov.x = oacc[i][j + 0] * inv;
            ov.y = oacc[i][j + 1] * inv;
            ov.z = oacc[i][j + 2] * inv;
            ov.w = oacc[i][j + 3] * inv;
            *(float4*)&ob[(size_t)r * DMODEL + tx * 8 + j] = ov;
        }
    }
}

// ---------------------------------------------------------------------------
extern "C" void kernel_launch(void* const* d_in, const int* in_sizes, int n_in,
                              void* d_out, int out_size)
{
    const float* x  = (const float*)d_in[0];
    const float* Wq = (const float*)d_in[1];
    const float* bq = (const float*)d_in[2];
    const float* Wk = (const float*)d_in[3];
    const float* bk = (const float*)d_in[4];
    const float* Wv = (const float*)d_in[5];
    const float* bv = (const float*)d_in[6];
    const float* Wo = (const float*)d_in[7];
    const float* bo = (const float*)d_in[8];
    float* out = (float*)d_out;

    float *qp, *kp, *vp, *ap;
    cudaGetSymbolAddress((void**)&qp, g_q);
    cudaGetSymbolAddress((void**)&kp, g_k);
    cudaGetSymbolAddress((void**)&vp, g_v);
    cudaGetSymbolAddress((void**)&ap, g_att);

    cudaFuncSetAttribute(flash_attn, cudaFuncAttributeMaxDynamicSharedMemorySize, FLASH_SMEM);

    dim3 gemm_grid(DMODEL / 128, ROWS / 128);   // (16, 32)
    sgemm_bias<<<gemm_grid, 256>>>(x, Wq, bq, qp);
    sgemm_bias<<<gemm_grid, 256>>>(x, Wk, bk, kp);
    sgemm_bias<<<gemm_grid, 256>>>(x, Wv, bv, vp);

    const int PAIRS = ROWS * HEADS * 64;
    rotary_kernel<<<(PAIRS + 255) / 256, 256>>>(qp, kp);

    dim3 attn_grid(NSEQ / BR, BATCH * HEADS);   // (32, 32)
    flash_attn<<<attn_grid, 256, FLASH_SMEM>>>(qp, kp, vp, ap);

    sgemm_bias<<<gemm_grid, 256>>>(ap, Wo, bo, out);
}

// round 3
// speedup vs baseline: 1.4076x; 1.4076x over previous
#include <cuda_runtime.h>
#include <cuda_bf16.h>
#include <math.h>
#include <stdint.h>

#define BATCH 2
#define NSEQ  2048
#define DMODEL 2048
#define HEADS 16
#define DHEAD 128
#define ROWS (BATCH*NSEQ)   // 4096

// ---------------------------------------------------------------------------
// scratch (device globals: no allocation allowed)
// ---------------------------------------------------------------------------
__device__ float g_q[ROWS*DMODEL];
__device__ float g_k[ROWS*DMODEL];
__device__ float g_v[ROWS*DMODEL];
__device__ float g_att[ROWS*DMODEL];

__device__ __nv_bfloat16 g_xhi[ROWS*DMODEL];
__device__ __nv_bfloat16 g_xlo[ROWS*DMODEL];
__device__ __nv_bfloat16 g_ahi[ROWS*DMODEL];
__device__ __nv_bfloat16 g_alo[ROWS*DMODEL];
__device__ __nv_bfloat16 g_wq_hi[DMODEL*DMODEL];
__device__ __nv_bfloat16 g_wq_lo[DMODEL*DMODEL];
__device__ __nv_bfloat16 g_wk_hi[DMODEL*DMODEL];
__device__ __nv_bfloat16 g_wk_lo[DMODEL*DMODEL];
__device__ __nv_bfloat16 g_wv_hi[DMODEL*DMODEL];
__device__ __nv_bfloat16 g_wv_lo[DMODEL*DMODEL];
__device__ __nv_bfloat16 g_wo_hi[DMODEL*DMODEL];
__device__ __nv_bfloat16 g_wo_lo[DMODEL*DMODEL];

// ---------------------------------------------------------------------------
// helpers
// ---------------------------------------------------------------------------
__device__ __forceinline__ uint32_t smem_u32(const void* p) {
    uint32_t a;
    asm("{ .reg .u64 t; cvta.to.shared.u64 t, %1; cvt.u32.u64 %0, t; }" : "=r"(a) : "l"(p));
    return a;
}

__device__ __forceinline__ void cp16(uint32_t dst, const void* src) {
    asm volatile("cp.async.cg.shared.global [%0], [%1], 16;" :: "r"(dst), "l"(src));
}
#define CP_COMMIT() asm volatile("cp.async.commit_group;" ::: "memory")
#define CP_WAIT(n)  asm volatile("cp.async.wait_group %0;" :: "n"(n) : "memory")

__device__ __forceinline__ void ldmx4(uint32_t addr, uint32_t& r0, uint32_t& r1,
                                      uint32_t& r2, uint32_t& r3) {
    asm volatile("ldmatrix.sync.aligned.m8n8.x4.shared.b16 {%0,%1,%2,%3}, [%4];"
                 : "=r"(r0), "=r"(r1), "=r"(r2), "=r"(r3) : "r"(addr));
}

__device__ __forceinline__ void mma16816(float& c0, float& c1, float& c2, float& c3,
                                         uint32_t a0, uint32_t a1, uint32_t a2, uint32_t a3,
                                         uint32_t b0, uint32_t b1) {
    asm volatile(
        "mma.sync.aligned.m16n8k16.row.col.f32.bf16.bf16.f32 "
        "{%0,%1,%2,%3}, {%4,%5,%6,%7}, {%8,%9}, {%0,%1,%2,%3};"
        : "+f"(c0), "+f"(c1), "+f"(c2), "+f"(c3)
        : "r"(a0), "r"(a1), "r"(a2), "r"(a3), "r"(b0), "r"(b1));
}

// ---------------------------------------------------------------------------
// split: fp32 -> (hi, lo) bf16 pair
// ---------------------------------------------------------------------------
__global__ __launch_bounds__(256)
void split_kernel(const float4* __restrict__ in, __nv_bfloat16* __restrict__ hi,
                  __nv_bfloat16* __restrict__ lo, int n4)
{
    int i = blockIdx.x * 256 + threadIdx.x;
    if (i >= n4) return;
    float4 v = in[i];
    __nv_bfloat16 h0 = __float2bfloat16(v.x);
    __nv_bfloat16 h1 = __float2bfloat16(v.y);
    __nv_bfloat16 h2 = __float2bfloat16(v.z);
    __nv_bfloat16 h3 = __float2bfloat16(v.w);
    __nv_bfloat162* hp = (__nv_bfloat162*)(hi + 4 * (size_t)i);
    hp[0] = __nv_bfloat162(h0, h1);
    hp[1] = __nv_bfloat162(h2, h3);
    __nv_bfloat162* lp = (__nv_bfloat162*)(lo + 4 * (size_t)i);
    lp[0] = __nv_bfloat162(__float2bfloat16(v.x - __bfloat162float(h0)),
                           __float2bfloat16(v.y - __bfloat162float(h1)));
    lp[1] = __nv_bfloat162(__float2bfloat16(v.z - __bfloat162float(h2)),
                           __float2bfloat16(v.w - __bfloat162float(h3)));
}

// ---------------------------------------------------------------------------
// transpose + split: W[K][N] fp32 -> Wt[N][K] bf16 (hi, lo)
// ---------------------------------------------------------------------------
__global__ __launch_bounds__(256)
void transpose_split(const float* __restrict__ W, __nv_bfloat16* __restrict__ th,
                     __nv_bfloat16* __restrict__ tl)
{
    __shared__ float t[32][33];
    int n0 = blockIdx.x * 32, k0 = blockIdx.y * 32;
    int tx = threadIdx.x & 31, ty = threadIdx.x >> 5;   // 32 x 8
#pragma unroll
    for (int i = 0; i < 32; i += 8)
        t[ty + i][tx] = W[(size_t)(k0 + ty + i) * DMODEL + n0 + tx];
    __syncthreads();
#pragma unroll
    for (int i = 0; i < 32; i += 8) {
        float v = t[tx][ty + i];
        __nv_bfloat16 h = __float2bfloat16(v);
        size_t o = (size_t)(n0 + ty + i) * DMODEL + k0 + tx;
        th[o] = h;
        tl[o] = __float2bfloat16(v - __bfloat162float(h));
    }
}

// ---------------------------------------------------------------------------
// mma.sync GEMM, split-bf16 x2 emulation (3 passes):
// C[4096, 2048] = (Ahi+Alo)[M,K] @ (Bhi+Blo)[N,K]^T + bias
// CTA 128x128, K-chunk 32, double-buffered cp.async.
// SMEM tiles: 128 rows x 32 bf16, row stride 40 bf16 (80B) -> conflict-free.
// ---------------------------------------------------------------------------
#define GK DMODEL
#define TM 128
#define TN 128
#define KC 32
#define RSTR 40                           // bf16 elements per smem row
#define TILE_B (128u * RSTR * 2u)         // 10240 bytes per tile
#define STAGE_B (4u * TILE_B)             // Ah, Al, Bh, Bl
#define GEMM_SMEM (2u * STAGE_B)          // 81920 bytes

__global__ __launch_bounds__(256)
void gemm_bf16x2(const __nv_bfloat16* __restrict__ Ahi, const __nv_bfloat16* __restrict__ Alo,
                 const __nv_bfloat16* __restrict__ Bhi, const __nv_bfloat16* __restrict__ Blo,
                 const float* __restrict__ bias, float* __restrict__ C)
{
    extern __shared__ __align__(128) char smem[];
    uint32_t sb = smem_u32(smem);
    const int tid  = threadIdx.x;
    const int wid  = tid >> 5;
    const int lane = tid & 31;
    const int brow = blockIdx.y * TM;
    const int bcol = blockIdx.x * TN;

    const int wm = wid & 1;       // 2 m-blocks of 64
    const int wn = wid >> 1;      // 4 n-blocks of 32

    float acc[4][4][4];
#pragma unroll
    for (int i = 0; i < 4; i++)
#pragma unroll
        for (int j = 0; j < 4; j++)
#pragma unroll
            for (int r = 0; r < 4; r++) acc[i][j][r] = 0.f;

    // copy chunk c into stage stg: 4 tiles of 128 rows x 64B (4 x 16B segs)
    auto copy_chunk = [&](int c, int stg) {
        int k0 = c * KC;
        uint32_t base = sb + (uint32_t)stg * STAGE_B;
        const __nv_bfloat16* srcs[4] = { Ahi, Alo, Bhi, Blo };
        int rows0[4] = { brow, brow, bcol, bcol };
#pragma unroll
        for (int t = 0; t < 4; t++) {
            const __nv_bfloat16* src = srcs[t] + (size_t)rows0[t] * GK + k0;
            uint32_t tb = base + (uint32_t)t * TILE_B;
#pragma unroll
            for (int i = 0; i < 2; i++) {
                int s = i * 256 + tid;       // 0..511
                int r = s >> 2, seg = s & 3;
                cp16(tb + (uint32_t)r * (RSTR * 2) + (uint32_t)seg * 16u,
                     src + (size_t)r * GK + seg * 8);
            }
        }
        CP_COMMIT();
    };

    const int NCH = GK / KC;   // 64
    copy_chunk(0, 0);

    // ldmatrix address pieces (same pattern for A and B tiles)
    const uint32_t lrow = (uint32_t)(lane & 15);
    const uint32_t lcol = (uint32_t)((lane >> 4) & 1) * 8u;

    for (int c = 0; c < NCH; c++) {
        int stg = c & 1;
        if (c + 1 < NCH) {
            copy_chunk(c + 1, stg ^ 1);
            CP_WAIT(1);
        } else {
            CP_WAIT(0);
        }
        __syncthreads();

        uint32_t base = sb + (uint32_t)stg * STAGE_B;
        uint32_t ah_b = base;
        uint32_t al_b = base + TILE_B;
        uint32_t bh_b = base + 2u * TILE_B;
        uint32_t bl_b = base + 3u * TILE_B;

#pragma unroll
        for (int kk = 0; kk < 2; kk++) {          // two k16 steps per chunk
            uint32_t koff = (uint32_t)(kk * 16) * 2u + lcol * 2u;

            // A hi/lo frags: 4 m-blocks of 16
            uint32_t Ah[4][4], Al[4][4];
#pragma unroll
            for (int mi = 0; mi < 4; mi++) {
                uint32_t roff = ((uint32_t)(wm * 64 + mi * 16) + lrow) * (RSTR * 2u) + koff;
                ldmx4(ah_b + roff, Ah[mi][0], Ah[mi][1], Ah[mi][2], Ah[mi][3]);
                ldmx4(al_b + roff, Al[mi][0], Al[mi][1], Al[mi][2], Al[mi][3]);
            }
            // B hi/lo frags: 4 n-blocks of 8 -> two x4 loads cover 16 n each
            uint32_t Bh[4][2], Bl[4][2];
#pragma unroll
            for (int np = 0; np < 2; np++) {
                uint32_t roff = ((uint32_t)(wn * 32 + np * 16) + lrow) * (RSTR * 2u) + koff;
                uint32_t r0, r1, r2, r3;
                ldmx4(bh_b + roff, r0, r1, r2, r3);
                Bh[np * 2][0] = r0; Bh[np * 2 + 1][0] = r1;
                Bh[np * 2][1] = r2; Bh[np * 2 + 1][1] = r3;
                ldmx4(bl_b + roff, r0, r1, r2, r3);
                Bl[np * 2][0] = r0; Bl[np * 2 + 1][0] = r1;
                Bl[np * 2][1] = r2; Bl[np * 2 + 1][1] = r3;
            }

#pragma unroll
            for (int mi = 0; mi < 4; mi++)
#pragma unroll
                for (int ni = 0; ni < 4; ni++) {
                    mma16816(acc[mi][ni][0], acc[mi][ni][1], acc[mi][ni][2], acc[mi][ni][3],
                             Ah[mi][0], Ah[mi][1], Ah[mi][2], Ah[mi][3],
                             Bh[ni][0], Bh[ni][1]);
                    mma16816(acc[mi][ni][0], acc[mi][ni][1], acc[mi][ni][2], acc[mi][ni][3],
                             Ah[mi][0], Ah[mi][1], Ah[mi][2], Ah[mi][3],
                             Bl[ni][0], Bl[ni][1]);
                    mma16816(acc[mi][ni][0], acc[mi][ni][1], acc[mi][ni][2], acc[mi][ni][3],
                             Al[mi][0], Al[mi][1], Al[mi][2], Al[mi][3],
                             Bh[ni][0], Bh[ni][1]);
                }
        }
        __syncthreads();
    }

    // epilogue
    int g = lane >> 2, t4 = lane & 3;
#pragma unroll
    for (int mi = 0; mi < 4; mi++) {
        int r0 = brow + wm * 64 + mi * 16 + g;
#pragma unroll
        for (int ni = 0; ni < 4; ni++) {
            int col = bcol + wn * 32 + ni * 8 + 2 * t4;
            float2 b01 = *(const float2*)&bias[col];
            float2 o0, o1;
            o0.x = acc[mi][ni][0] + b01.x;
            o0.y = acc[mi][ni][1] + b01.y;
            o1.x = acc[mi][ni][2] + b01.x;
            o1.y = acc[mi][ni][3] + b01.y;
            *(float2*)&C[(size_t)r0 * DMODEL + col]       = o0;
            *(float2*)&C[(size_t)(r0 + 8) * DMODEL + col] = o1;
        }
    }
}

// ---------------------------------------------------------------------------
// Rotary: in-place on q (with scale) and k; pair (d, d+64) shares one angle.
// ---------------------------------------------------------------------------
__global__ __launch_bounds__(256)
void rotary_kernel(float* __restrict__ q, float* __restrict__ k)
{
    int idx = blockIdx.x * blockDim.x + threadIdx.x;
    const int PAIRS = ROWS * HEADS * 64;
    if (idx >= PAIRS) return;

    int row = idx / (HEADS * 64);
    int rem = idx % (HEADS * 64);
    int h = rem >> 6;
    int d = rem & 63;
    int n = row % NSEQ;

    float inv_freq = __expf(-((float)(2 * d) / 128.0f) * 9.210340371976184f);
    float ang = (float)n * inv_freq;
    float s, c;
    sincosf(ang, &s, &c);

    size_t base = (size_t)row * DMODEL + h * DHEAD + d;
    const float scale = 0.08838834764831845f;  // 128^-0.5

    float q1 = q[base], q2 = q[base + 64];
    q[base]      = (q1 * c - q2 * s) * scale;
    q[base + 64] = (q2 * c + q1 * s) * scale;

    float k1 = k[base], k2 = k[base + 64];
    k[base]      = k1 * c - k2 * s;
    k[base + 64] = k2 * c + k1 * s;
}

// ---------------------------------------------------------------------------
// Flash attention (causal), fp32. Br = Bc = 64, 256 threads.
// ---------------------------------------------------------------------------
#define BR 64
#define BC 64
#define QK_PAD 132
#define S_PAD  68
#define FLASH_SMEM ((3 * BR * QK_PAD + BR * S_PAD + 3 * BR) * 4)

__global__ __launch_bounds__(256)
void flash_attn(const float* __restrict__ q, const float* __restrict__ k,
                const float* __restrict__ v, float* __restrict__ o)
{
    extern __shared__ float sm[];
    float* Qs   = sm;
    float* Ks   = Qs + BR * QK_PAD;
    float* Vs   = Ks + BR * QK_PAD;
    float* Ss   = Vs + BR * QK_PAD;
    float* mrow = Ss + BR * S_PAD;
    float* lrow = mrow + BR;
    float* fac  = lrow + BR;

    int tid = threadIdx.x;
    int it  = blockIdx.x;
    int bh  = blockIdx.y;
    int b = bh >> 4, h = bh & 15;

    const float* qb = q + (size_t)b * NSEQ * DMODEL + h * DHEAD;
    const float* kb = k + (size_t)b * NSEQ * DMODEL + h * DHEAD;
    const float* vb = v + (size_t)b * NSEQ * DMODEL + h * DHEAD;
    float*       ob = o + (size_t)b * NSEQ * DMODEL + h * DHEAD;

    int i0 = it * BR;

    for (int x = tid; x < BR * 32; x += 256) {
        int r = x >> 5, c4 = (x & 31) << 2;
        *(float4*)&Qs[r * QK_PAD + c4] = *(const float4*)&qb[(size_t)(i0 + r) * DMODEL + c4];
    }
    if (tid < BR) { mrow[tid] = -INFINITY; lrow[tid] = 0.f; }

    float oacc[4][8];
#pragma unroll
    for (int i = 0; i < 4; i++)
#pragma unroll
        for (int j = 0; j < 8; j++) oacc[i][j] = 0.f;

    int ty = tid >> 4, tx = tid & 15;
    __syncthreads();

    for (int jt = 0; jt <= it; jt++) {
        int j0 = jt * BC;
        for (int x = tid; x < BC * 32; x += 256) {
            int r = x >> 5, c4 = (x & 31) << 2;
            *(float4*)&Ks[r * QK_PAD + c4] = *(const float4*)&kb[(size_t)(j0 + r) * DMODEL + c4];
            *(float4*)&Vs[r * QK_PAD + c4] = *(const float4*)&vb[(size_t)(j0 + r) * DMODEL + c4];
        }
        __syncthreads();

        float s4[4][4];
#pragma unroll
        for (int i = 0; i < 4; i++)
#pragma unroll
            for (int j = 0; j < 4; j++) s4[i][j] = 0.f;

        for (int d = 0; d < DHEAD; d++) {
            float a[4], bb[4];
#pragma unroll
            for (int i = 0; i < 4; i++) a[i]  = Qs[(ty * 4 + i) * QK_PAD + d];
#pragma unroll
            for (int j = 0; j < 4; j++) bb[j] = Ks[(tx * 4 + j) * QK_PAD + d];
#pragma unroll
            for (int i = 0; i < 4; i++)
#pragma unroll
                for (int j = 0; j < 4; j++)
                    s4[i][j] += a[i] * bb[j];
        }

        if (jt == it) {
#pragma unroll
            for (int i = 0; i < 4; i++)
#pragma unroll
                for (int j = 0; j < 4; j++)
                    if (j0 + tx * 4 + j > i0 + ty * 4 + i) s4[i][j] = -INFINITY;
        }

#pragma unroll
        for (int i = 0; i < 4; i++)
#pragma unroll
            for (int j = 0; j < 4; j++)
                Ss[(ty * 4 + i) * S_PAD + tx * 4 + j] = s4[i][j];
        __syncthreads();

        if (tid < BR) {
            float m_old = mrow[tid];
            float mx = m_old;
            for (int j = 0; j < BC; j++) mx = fmaxf(mx, Ss[tid * S_PAD + j]);
            float f = __expf(m_old - mx);
            float sum = 0.f;
            for (int j = 0; j < BC; j++) {
                float p = __expf(Ss[tid * S_PAD + j] - mx);
                Ss[tid * S_PAD + j] = p;
                sum += p;
            }
            mrow[tid] = mx;
            lrow[tid] = lrow[tid] * f + sum;
            fac[tid]  = f;
        }
        __syncthreads();

#pragma unroll
        for (int i = 0; i < 4; i++) {
            float f = fac[ty * 4 + i];
#pragma unroll
            for (int j = 0; j < 8; j++) oacc[i][j] *= f;
        }
        for (int jj = 0; jj < BC; jj++) {
            float p[4], vv[8];
#pragma unroll
            for (int i = 0; i < 4; i++) p[i] = Ss[(ty * 4 + i) * S_PAD + jj];
#pragma unroll
            for (int j = 0; j < 8; j++) vv[j] = Vs[jj * QK_PAD + tx * 8 + j];
#pragma unroll
            for (int i = 0; i < 4; i++)
#pragma unroll
                for (int j = 0; j < 8; j++)
                    oacc[i][j] += p[i] * vv[j];
        }
        __syncthreads();
    }

#pragma unroll
    for (int i = 0; i < 4; i++) {
        float inv = 1.0f / lrow[ty * 4 + i];
        int r = i0 + ty * 4 + i;
#pragma unroll
        for (int j = 0; j < 8; j += 4) {
            float4 ov;
            ov.x = oacc[i][j + 0] * inv;
            ov.y = oacc[i][j + 1] * inv;
            ov.z = oacc[i][j + 2] * inv;
            ov.w = oacc[i][j + 3] * inv;
            *(float4*)&ob[(size_t)r * DMODEL + tx * 8 + j] = ov;
        }
    }
}

// ---------------------------------------------------------------------------
extern "C" void kernel_launch(void* const* d_in, const int* in_sizes, int n_in,
                              void* d_out, int out_size)
{
    const float* x  = (const float*)d_in[0];
    const float* Wq = (const float*)d_in[1];
    const float* bq = (const float*)d_in[2];
    const float* Wk = (const float*)d_in[3];
    const float* bk = (const float*)d_in[4];
    const float* Wv = (const float*)d_in[5];
    const float* bv = (const float*)d_in[6];
    const float* Wo = (const float*)d_in[7];
    const float* bo = (const float*)d_in[8];
    float* out = (float*)d_out;

    float *qp, *kp, *vp, *ap;
    cudaGetSymbolAddress((void**)&qp, g_q);
    cudaGetSymbolAddress((void**)&kp, g_k);
    cudaGetSymbolAddress((void**)&vp, g_v);
    cudaGetSymbolAddress((void**)&ap, g_att);
    __nv_bfloat16 *xhi, *xlo, *ahi, *alo;
    __nv_bfloat16 *wqh, *wql, *wkh, *wkl, *wvh, *wvl, *woh, *wol;
    cudaGetSymbolAddress((void**)&xhi, g_xhi);
    cudaGetSymbolAddress((void**)&xlo, g_xlo);
    cudaGetSymbolAddress((void**)&ahi, g_ahi);
    cudaGetSymbolAddress((void**)&alo, g_alo);
    cudaGetSymbolAddress((void**)&wqh, g_wq_hi);
    cudaGetSymbolAddress((void**)&wql, g_wq_lo);
    cudaGetSymbolAddress((void**)&wkh, g_wk_hi);
    cudaGetSymbolAddress((void**)&wkl, g_wk_lo);
    cudaGetSymbolAddress((void**)&wvh, g_wv_hi);
    cudaGetSymbolAddress((void**)&wvl, g_wv_lo);
    cudaGetSymbolAddress((void**)&woh, g_wo_hi);
    cudaGetSymbolAddress((void**)&wol, g_wo_lo);

    cudaFuncSetAttribute(flash_attn, cudaFuncAttributeMaxDynamicSharedMemorySize, FLASH_SMEM);
    cudaFuncSetAttribute(gemm_bf16x2, cudaFuncAttributeMaxDynamicSharedMemorySize, GEMM_SMEM);

    // prep: split x, transpose+split weights
    int n4x = ROWS * DMODEL / 4;
    split_kernel<<<(n4x + 255) / 256, 256>>>((const float4*)x, xhi, xlo, n4x);
    dim3 tgrid(DMODEL / 32, DMODEL / 32);
    transpose_split<<<tgrid, 256>>>(Wq, wqh, wql);
    transpose_split<<<tgrid, 256>>>(Wk, wkh, wkl);
    transpose_split<<<tgrid, 256>>>(Wv, wvh, wvl);
    transpose_split<<<tgrid, 256>>>(Wo, woh, wol);

    // QKV projections on tensor cores
    dim3 ggrid(DMODEL / TN, ROWS / TM);   // (16, 32)
    gemm_bf16x2<<<ggrid, 256, GEMM_SMEM>>>(xhi, xlo, wqh, wql, bq, qp);
    gemm_bf16x2<<<ggrid, 256, GEMM_SMEM>>>(xhi, xlo, wkh, wkl, bk, kp);
    gemm_bf16x2<<<ggrid, 256, GEMM_SMEM>>>(xhi, xlo, wvh, wvl, bv, vp);

    const int PAIRS = ROWS * HEADS * 64;
    rotary_kernel<<<(PAIRS + 255) / 256, 256>>>(qp, kp);

    dim3 attn_grid(NSEQ / BR, BATCH * HEADS);
    flash_attn<<<attn_grid, 256, FLASH_SMEM>>>(qp, kp, vp, ap);

    // output projection
    split_kernel<<<(n4x + 255) / 256, 256>>>((const float4*)ap, ahi, alo, n4x);
    gemm_bf16x2<<<ggrid, 256, GEMM_SMEM>>>(ahi, alo, woh, wol, bo, out);
}

// round 4
// speedup vs baseline: 3.3652x; 2.3908x over previous
#include <cuda_runtime.h>
#include <cuda_bf16.h>
#include <math.h>
#include <stdint.h>

#define BATCH 2
#define NSEQ  2048
#define DMODEL 2048
#define HEADS 16
#define DHEAD 128
#define ROWS (BATCH*NSEQ)   // 4096

// ---------------------------------------------------------------------------
// scratch (device globals: no allocation allowed)
// ---------------------------------------------------------------------------
__device__ float g_q[ROWS*DMODEL];
__device__ float g_k[ROWS*DMODEL];
__device__ float g_v[ROWS*DMODEL];
__device__ float g_att[ROWS*DMODEL];

__device__ __nv_bfloat16 g_xhi[ROWS*DMODEL];
__device__ __nv_bfloat16 g_xlo[ROWS*DMODEL];
__device__ __nv_bfloat16 g_ahi[ROWS*DMODEL];
__device__ __nv_bfloat16 g_alo[ROWS*DMODEL];
__device__ __nv_bfloat16 g_qh[ROWS*DMODEL];
__device__ __nv_bfloat16 g_ql[ROWS*DMODEL];
__device__ __nv_bfloat16 g_kh[ROWS*DMODEL];
__device__ __nv_bfloat16 g_kl[ROWS*DMODEL];
__device__ __nv_bfloat16 g_vh[ROWS*DMODEL];
__device__ __nv_bfloat16 g_vl[ROWS*DMODEL];
__device__ __nv_bfloat16 g_wq_hi[DMODEL*DMODEL];
__device__ __nv_bfloat16 g_wq_lo[DMODEL*DMODEL];
__device__ __nv_bfloat16 g_wk_hi[DMODEL*DMODEL];
__device__ __nv_bfloat16 g_wk_lo[DMODEL*DMODEL];
__device__ __nv_bfloat16 g_wv_hi[DMODEL*DMODEL];
__device__ __nv_bfloat16 g_wv_lo[DMODEL*DMODEL];
__device__ __nv_bfloat16 g_wo_hi[DMODEL*DMODEL];
__device__ __nv_bfloat16 g_wo_lo[DMODEL*DMODEL];

// ---------------------------------------------------------------------------
// helpers
// ---------------------------------------------------------------------------
__device__ __forceinline__ uint32_t smem_u32(const void* p) {
    uint32_t a;
    asm("{ .reg .u64 t; cvta.to.shared.u64 t, %1; cvt.u32.u64 %0, t; }" : "=r"(a) : "l"(p));
    return a;
}

__device__ __forceinline__ void cp16(uint32_t dst, const void* src) {
    asm volatile("cp.async.cg.shared.global [%0], [%1], 16;" :: "r"(dst), "l"(src));
}
#define CP_COMMIT() asm volatile("cp.async.commit_group;" ::: "memory")
#define CP_WAIT(n)  asm volatile("cp.async.wait_group %0;" :: "n"(n) : "memory")

__device__ __forceinline__ void ldmx4(uint32_t addr, uint32_t& r0, uint32_t& r1,
                                      uint32_t& r2, uint32_t& r3) {
    asm volatile("ldmatrix.sync.aligned.m8n8.x4.shared.b16 {%0,%1,%2,%3}, [%4];"
                 : "=r"(r0), "=r"(r1), "=r"(r2), "=r"(r3) : "r"(addr));
}
__device__ __forceinline__ void ldmx4t(uint32_t addr, uint32_t& r0, uint32_t& r1,
                                       uint32_t& r2, uint32_t& r3) {
    asm volatile("ldmatrix.sync.aligned.m8n8.x4.trans.shared.b16 {%0,%1,%2,%3}, [%4];"
                 : "=r"(r0), "=r"(r1), "=r"(r2), "=r"(r3) : "r"(addr));
}

__device__ __forceinline__ void mma16816(float& c0, float& c1, float& c2, float& c3,
                                         uint32_t a0, uint32_t a1, uint32_t a2, uint32_t a3,
                                         uint32_t b0, uint32_t b1) {
    asm volatile(
        "mma.sync.aligned.m16n8k16.row.col.f32.bf16.bf16.f32 "
        "{%0,%1,%2,%3}, {%4,%5,%6,%7}, {%8,%9}, {%0,%1,%2,%3};"
        : "+f"(c0), "+f"(c1), "+f"(c2), "+f"(c3)
        : "r"(a0), "r"(a1), "r"(a2), "r"(a3), "r"(b0), "r"(b1));
}

__device__ __forceinline__ uint32_t packbf(float a, float b) {
    __nv_bfloat162 t = __floats2bfloat162_rn(a, b);
    return *(uint32_t*)&t;
}

// ---------------------------------------------------------------------------
// split: fp32 -> (hi, lo) bf16 pair
// ---------------------------------------------------------------------------
__global__ __launch_bounds__(256)
void split_kernel(const float4* __restrict__ in, __nv_bfloat16* __restrict__ hi,
                  __nv_bfloat16* __restrict__ lo, int n4)
{
    int i = blockIdx.x * 256 + threadIdx.x;
    if (i >= n4) return;
    float4 v = in[i];
    __nv_bfloat16 h0 = __float2bfloat16(v.x);
    __nv_bfloat16 h1 = __float2bfloat16(v.y);
    __nv_bfloat16 h2 = __float2bfloat16(v.z);
    __nv_bfloat16 h3 = __float2bfloat16(v.w);
    __nv_bfloat162* hp = (__nv_bfloat162*)(hi + 4 * (size_t)i);
    hp[0] = __nv_bfloat162(h0, h1);
    hp[1] = __nv_bfloat162(h2, h3);
    __nv_bfloat162* lp = (__nv_bfloat162*)(lo + 4 * (size_t)i);
    lp[0] = __nv_bfloat162(__float2bfloat16(v.x - __bfloat162float(h0)),
                           __float2bfloat16(v.y - __bfloat162float(h1)));
    lp[1] = __nv_bfloat162(__float2bfloat16(v.z - __bfloat162float(h2)),
                           __float2bfloat16(v.w - __bfloat162float(h3)));
}

// ---------------------------------------------------------------------------
// transpose + split: W[K][N] fp32 -> Wt[N][K] bf16 (hi, lo)
// ---------------------------------------------------------------------------
__global__ __launch_bounds__(256)
void transpose_split(const float* __restrict__ W, __nv_bfloat16* __restrict__ th,
                     __nv_bfloat16* __restrict__ tl)
{
    __shared__ float t[32][33];
    int n0 = blockIdx.x * 32, k0 = blockIdx.y * 32;
    int tx = threadIdx.x & 31, ty = threadIdx.x >> 5;   // 32 x 8
#pragma unroll
    for (int i = 0; i < 32; i += 8)
        t[ty + i][tx] = W[(size_t)(k0 + ty + i) * DMODEL + n0 + tx];
    __syncthreads();
#pragma unroll
    for (int i = 0; i < 32; i += 8) {
        float v = t[tx][ty + i];
        __nv_bfloat16 h = __float2bfloat16(v);
        size_t o = (size_t)(n0 + ty + i) * DMODEL + k0 + tx;
        th[o] = h;
        tl[o] = __float2bfloat16(v - __bfloat162float(h));
    }
}

// ---------------------------------------------------------------------------
// mma.sync GEMM, split-bf16 x2 emulation (3 passes) — unchanged from R3
// ---------------------------------------------------------------------------
#define GK DMODEL
#define TM 128
#define TN 128
#define KC 32
#define RSTR 40
#define TILE_B (128u * RSTR * 2u)
#define STAGE_B (4u * TILE_B)
#define GEMM_SMEM (2u * STAGE_B)

__global__ __launch_bounds__(256)
void gemm_bf16x2(const __nv_bfloat16* __restrict__ Ahi, const __nv_bfloat16* __restrict__ Alo,
                 const __nv_bfloat16* __restrict__ Bhi, const __nv_bfloat16* __restrict__ Blo,
                 const float* __restrict__ bias, float* __restrict__ C)
{
    extern __shared__ __align__(128) char smem[];
    uint32_t sb = smem_u32(smem);
    const int tid  = threadIdx.x;
    const int wid  = tid >> 5;
    const int lane = tid & 31;
    const int brow = blockIdx.y * TM;
    const int bcol = blockIdx.x * TN;

    const int wm = wid & 1;
    const int wn = wid >> 1;

    float acc[4][4][4];
#pragma unroll
    for (int i = 0; i < 4; i++)
#pragma unroll
        for (int j = 0; j < 4; j++)
#pragma unroll
            for (int r = 0; r < 4; r++) acc[i][j][r] = 0.f;

    auto copy_chunk = [&](int c, int stg) {
        int k0 = c * KC;
        uint32_t base = sb + (uint32_t)stg * STAGE_B;
        const __nv_bfloat16* srcs[4] = { Ahi, Alo, Bhi, Blo };
        int rows0[4] = { brow, brow, bcol, bcol };
#pragma unroll
        for (int t = 0; t < 4; t++) {
            const __nv_bfloat16* src = srcs[t] + (size_t)rows0[t] * GK + k0;
            uint32_t tb = base + (uint32_t)t * TILE_B;
#pragma unroll
            for (int i = 0; i < 2; i++) {
                int s = i * 256 + tid;
                int r = s >> 2, seg = s & 3;
                cp16(tb + (uint32_t)r * (RSTR * 2) + (uint32_t)seg * 16u,
                     src + (size_t)r * GK + seg * 8);
            }
        }
        CP_COMMIT();
    };

    const int NCH = GK / KC;
    copy_chunk(0, 0);

    const uint32_t lrow = (uint32_t)(lane & 15);
    const uint32_t lcol = (uint32_t)((lane >> 4) & 1) * 8u;

    for (int c = 0; c < NCH; c++) {
        int stg = c & 1;
        if (c + 1 < NCH) {
            copy_chunk(c + 1, stg ^ 1);
            CP_WAIT(1);
        } else {
            CP_WAIT(0);
        }
        __syncthreads();

        uint32_t base = sb + (uint32_t)stg * STAGE_B;
        uint32_t ah_b = base;
        uint32_t al_b = base + TILE_B;
        uint32_t bh_b = base + 2u * TILE_B;
        uint32_t bl_b = base + 3u * TILE_B;

#pragma unroll
        for (int kk = 0; kk < 2; kk++) {
            uint32_t koff = (uint32_t)(kk * 16) * 2u + lcol * 2u;

            uint32_t Ah[4][4], Al[4][4];
#pragma unroll
            for (int mi = 0; mi < 4; mi++) {
                uint32_t roff = ((uint32_t)(wm * 64 + mi * 16) + lrow) * (RSTR * 2u) + koff;
                ldmx4(ah_b + roff, Ah[mi][0], Ah[mi][1], Ah[mi][2], Ah[mi][3]);
                ldmx4(al_b + roff, Al[mi][0], Al[mi][1], Al[mi][2], Al[mi][3]);
            }
            uint32_t Bh[4][2], Bl[4][2];
#pragma unroll
            for (int np = 0; np < 2; np++) {
                uint32_t roff = ((uint32_t)(wn * 32 + np * 16) + lrow) * (RSTR * 2u) + koff;
                uint32_t r0, r1, r2, r3;
                ldmx4(bh_b + roff, r0, r1, r2, r3);
                Bh[np * 2][0] = r0; Bh[np * 2 + 1][0] = r1;
                Bh[np * 2][1] = r2; Bh[np * 2 + 1][1] = r3;
                ldmx4(bl_b + roff, r0, r1, r2, r3);
                Bl[np * 2][0] = r0; Bl[np * 2 + 1][0] = r1;
                Bl[np * 2][1] = r2; Bl[np * 2 + 1][1] = r3;
            }

#pragma unroll
            for (int mi = 0; mi < 4; mi++)
#pragma unroll
                for (int ni = 0; ni < 4; ni++) {
                    mma16816(acc[mi][ni][0], acc[mi][ni][1], acc[mi][ni][2], acc[mi][ni][3],
                             Ah[mi][0], Ah[mi][1], Ah[mi][2], Ah[mi][3],
                             Bh[ni][0], Bh[ni][1]);
                    mma16816(acc[mi][ni][0], acc[mi][ni][1], acc[mi][ni][2], acc[mi][ni][3],
                             Ah[mi][0], Ah[mi][1], Ah[mi][2], Ah[mi][3],
                             Bl[ni][0], Bl[ni][1]);
                    mma16816(acc[mi][ni][0], acc[mi][ni][1], acc[mi][ni][2], acc[mi][ni][3],
                             Al[mi][0], Al[mi][1], Al[mi][2], Al[mi][3],
                             Bh[ni][0], Bh[ni][1]);
                }
        }
        __syncthreads();
    }

    int g = lane >> 2, t4 = lane & 3;
#pragma unroll
    for (int mi = 0; mi < 4; mi++) {
        int r0 = brow + wm * 64 + mi * 16 + g;
#pragma unroll
        for (int ni = 0; ni < 4; ni++) {
            int col = bcol + wn * 32 + ni * 8 + 2 * t4;
            float2 b01 = *(const float2*)&bias[col];
            float2 o0, o1;
            o0.x = acc[mi][ni][0] + b01.x;
            o0.y = acc[mi][ni][1] + b01.y;
            o1.x = acc[mi][ni][2] + b01.x;
            o1.y = acc[mi][ni][3] + b01.y;
            *(float2*)&C[(size_t)r0 * DMODEL + col]       = o0;
            *(float2*)&C[(size_t)(r0 + 8) * DMODEL + col] = o1;
        }
    }
}

// ---------------------------------------------------------------------------
// Rotary + split to bf16 hi/lo: q (scaled) and k
// ---------------------------------------------------------------------------
__global__ __launch_bounds__(256)
void rotary_split(const float* __restrict__ q, const float* __restrict__ k,
                  __nv_bfloat16* __restrict__ qh, __nv_bfloat16* __restrict__ ql,
                  __nv_bfloat16* __restrict__ kh, __nv_bfloat16* __restrict__ kl)
{
    int idx = blockIdx.x * blockDim.x + threadIdx.x;
    const int PAIRS = ROWS * HEADS * 64;
    if (idx >= PAIRS) return;

    int row = idx / (HEADS * 64);
    int rem = idx % (HEADS * 64);
    int h = rem >> 6;
    int d = rem & 63;
    int n = row % NSEQ;

    float inv_freq = __expf(-((float)(2 * d) / 128.0f) * 9.210340371976184f);
    float ang = (float)n * inv_freq;
    float s, c;
    sincosf(ang, &s, &c);

    size_t base = (size_t)row * DMODEL + h * DHEAD + d;
    const float scale = 0.08838834764831845f;  // 128^-0.5

    float q1 = q[base], q2 = q[base + 64];
    float qa = (q1 * c - q2 * s) * scale;
    float qb2 = (q2 * c + q1 * s) * scale;
    __nv_bfloat16 hh = __float2bfloat16(qa);
    qh[base] = hh; ql[base] = __float2bfloat16(qa - __bfloat162float(hh));
    hh = __float2bfloat16(qb2);
    qh[base + 64] = hh; ql[base + 64] = __float2bfloat16(qb2 - __bfloat162float(hh));

    float k1 = k[base], k2 = k[base + 64];
    float ka = k1 * c - k2 * s;
    float kb2 = k2 * c + k1 * s;
    hh = __float2bfloat16(ka);
    kh[base] = hh; kl[base] = __float2bfloat16(ka - __bfloat162float(hh));
    hh = __float2bfloat16(kb2);
    kh[base + 64] = hh; kl[base + 64] = __float2bfloat16(kb2 - __bfloat162float(hh));
}

// ---------------------------------------------------------------------------
// Flash attention (causal) with mma.sync, split-bf16 (3 passes each mma).
// BR=BC=64, 128 threads (4 warps x 16 q-rows).
// ---------------------------------------------------------------------------
#define ASTR 136                        // bf16 elems per smem row (272B)
#define ATILE_B (64u * ASTR * 2u)       // 17408 B
#define ATT_SMEM (6u * ATILE_B)         // 104448 B

__global__ __launch_bounds__(128)
void flash_attn_mma(const __nv_bfloat16* __restrict__ qh, const __nv_bfloat16* __restrict__ ql,
                    const __nv_bfloat16* __restrict__ kh, const __nv_bfloat16* __restrict__ kl,
                    const __nv_bfloat16* __restrict__ vh, const __nv_bfloat16* __restrict__ vl,
                    float* __restrict__ o)
{
    extern __shared__ __align__(128) char smem[];
    uint32_t sb = smem_u32(smem);
    uint32_t sQh = sb, sQl = sb + ATILE_B;
    uint32_t sKh = sb + 2u * ATILE_B, sKl = sb + 3u * ATILE_B;
    uint32_t sVh = sb + 4u * ATILE_B, sVl = sb + 5u * ATILE_B;

    const int tid  = threadIdx.x;
    const int warp = tid >> 5;
    const int lane = tid & 31;
    const int g    = lane >> 2;
    const int q4   = lane & 3;

    const int it = blockIdx.x;
    const int bh = blockIdx.y;
    const int b = bh >> 4, h = bh & 15;
    const int i0 = it * 64;

    const size_t hoff = (size_t)b * NSEQ * DMODEL + h * DHEAD;
    const __nv_bfloat16* qhb = qh + hoff;
    const __nv_bfloat16* qlb = ql + hoff;
    const __nv_bfloat16* khb = kh + hoff;
    const __nv_bfloat16* klb = kl + hoff;
    const __nv_bfloat16* vhb = vh + hoff;
    const __nv_bfloat16* vlb = vl + hoff;

    // preload Q hi/lo: 64 rows x 256B, 1024 cp16 per array
    {
        const __nv_bfloat16* srcs[2] = { qhb, qlb };
        uint32_t dsts[2] = { sQh, sQl };
#pragma unroll
        for (int t = 0; t < 2; t++)
#pragma unroll
            for (int i = 0; i < 8; i++) {
                int s = i * 128 + tid;
                int r = s >> 4, seg = s & 15;
                cp16(dsts[t] + (uint32_t)r * 272u + (uint32_t)seg * 16u,
                     srcs[t] + (size_t)(i0 + r) * DMODEL + seg * 8);
            }
        CP_COMMIT();
    }

    float m0 = -1e30f, m1 = -1e30f, l0 = 0.f, l1 = 0.f;
    float oa[16][4];
#pragma unroll
    for (int d = 0; d < 16; d++)
#pragma unroll
        for (int r = 0; r < 4; r++) oa[d][r] = 0.f;

    const uint32_t lrow = (uint32_t)(lane & 15);
    const uint32_t lseg16 = (uint32_t)(lane >> 4) * 16u;

    for (int jt = 0; jt <= it; jt++) {
        int j0 = jt * 64;
        // load K/V hi/lo tiles
        {
            const __nv_bfloat16* srcs[4] = { khb, klb, vhb, vlb };
            uint32_t dsts[4] = { sKh, sKl, sVh, sVl };
#pragma unroll
            for (int t = 0; t < 4; t++)
#pragma unroll
                for (int i = 0; i < 8; i++) {
                    int s = i * 128 + tid;
                    int r = s >> 4, seg = s & 15;
                    cp16(dsts[t] + (uint32_t)r * 272u + (uint32_t)seg * 16u,
                         srcs[t] + (size_t)(j0 + r) * DMODEL + seg * 8);
                }
            CP_COMMIT();
        }
        CP_WAIT(0);
        __syncthreads();

        // ---- S = Qh*Kh + Qh*Kl + Ql*Kh : s[8][4] ----
        float s[8][4];
#pragma unroll
        for (int nb = 0; nb < 8; nb++)
#pragma unroll
            for (int r = 0; r < 4; r++) s[nb][r] = 0.f;

        for (int kk = 0; kk < 8; kk++) {
            uint32_t qoff = ((uint32_t)(warp * 16) + lrow) * 272u + lseg16 + (uint32_t)kk * 32u;
            uint32_t Qh4[4], Ql4[4];
            ldmx4(sQh + qoff, Qh4[0], Qh4[1], Qh4[2], Qh4[3]);
            ldmx4(sQl + qoff, Ql4[0], Ql4[1], Ql4[2], Ql4[3]);
#pragma unroll
            for (int np = 0; np < 4; np++) {
                uint32_t koff = ((uint32_t)(np * 16) + lrow) * 272u + lseg16 + (uint32_t)kk * 32u;
                uint32_t h0, h1, h2, h3, l0r, l1r, l2r, l3r;
                ldmx4(sKh + koff, h0, h1, h2, h3);
                ldmx4(sKl + koff, l0r, l1r, l2r, l3r);
                int nb = np * 2;
                mma16816(s[nb][0], s[nb][1], s[nb][2], s[nb][3],
                         Qh4[0], Qh4[1], Qh4[2], Qh4[3], h0, h2);
                mma16816(s[nb][0], s[nb][1], s[nb][2], s[nb][3],
                         Qh4[0], Qh4[1], Qh4[2], Qh4[3], l0r, l2r);
                mma16816(s[nb][0], s[nb][1], s[nb][2], s[nb][3],
                         Ql4[0], Ql4[1], Ql4[2], Ql4[3], h0, h2);
                mma16816(s[nb + 1][0], s[nb + 1][1], s[nb + 1][2], s[nb + 1][3],
                         Qh4[0], Qh4[1], Qh4[2], Qh4[3], h1, h3);
                mma16816(s[nb + 1][0], s[nb + 1][1], s[nb + 1][2], s[nb + 1][3],
                         Qh4[0], Qh4[1], Qh4[2], Qh4[3], l1r, l3r);
                mma16816(s[nb + 1][0], s[nb + 1][1], s[nb + 1][2], s[nb + 1][3],
                         Ql4[0], Ql4[1], Ql4[2], Ql4[3], h1, h3);
            }
        }

        // ---- causal mask on diagonal tile ----
        if (jt == it) {
            int r0 = warp * 16 + g;      // local row of regs [0],[1]
            int r1 = r0 + 8;             // regs [2],[3]
#pragma unroll
            for (int nb = 0; nb < 8; nb++) {
                int c0 = nb * 8 + 2 * q4;
                if (c0 > r0)     s[nb][0] = -1e30f;
                if (c0 + 1 > r0) s[nb][1] = -1e30f;
                if (c0 > r1)     s[nb][2] = -1e30f;
                if (c0 + 1 > r1) s[nb][3] = -1e30f;
            }
        }

        // ---- online softmax (rows g and g+8 of this warp) ----
        float mx0 = -1e30f, mx1 = -1e30f;
#pragma unroll
        for (int nb = 0; nb < 8; nb++) {
            mx0 = fmaxf(mx0, fmaxf(s[nb][0], s[nb][1]));
            mx1 = fmaxf(mx1, fmaxf(s[nb][2], s[nb][3]));
        }
        mx0 = fmaxf(mx0, __shfl_xor_sync(0xffffffffu, mx0, 1));
        mx0 = fmaxf(mx0, __shfl_xor_sync(0xffffffffu, mx0, 2));
        mx1 = fmaxf(mx1, __shfl_xor_sync(0xffffffffu, mx1, 1));
        mx1 = fmaxf(mx1, __shfl_xor_sync(0xffffffffu, mx1, 2));

        float m0n = fmaxf(m0, mx0), m1n = fmaxf(m1, mx1);
        float f0 = __expf(m0 - m0n), f1 = __expf(m1 - m1n);

        float sum0 = 0.f, sum1 = 0.f;
#pragma unroll
        for (int nb = 0; nb < 8; nb++) {
            s[nb][0] = __expf(s[nb][0] - m0n);
            s[nb][1] = __expf(s[nb][1] - m0n);
            s[nb][2] = __expf(s[nb][2] - m1n);
            s[nb][3] = __expf(s[nb][3] - m1n);
            sum0 += s[nb][0] + s[nb][1];
            sum1 += s[nb][2] + s[nb][3];
        }
        sum0 += __shfl_xor_sync(0xffffffffu, sum0, 1);
        sum0 += __shfl_xor_sync(0xffffffffu, sum0, 2);
        sum1 += __shfl_xor_sync(0xffffffffu, sum1, 1);
        sum1 += __shfl_xor_sync(0xffffffffu, sum1, 2);

        m0 = m0n; m1 = m1n;
        l0 = l0 * f0 + sum0;
        l1 = l1 * f1 + sum1;

#pragma unroll
        for (int d = 0; d < 16; d++) {
            oa[d][0] *= f0; oa[d][1] *= f0;
            oa[d][2] *= f1; oa[d][3] *= f1;
        }

        // ---- P -> bf16 hi/lo A-frags (C-frag == A-frag identity) ----
        uint32_t Ph[4][4], Pl[4][4];
#pragma unroll
        for (int kk2 = 0; kk2 < 4; kk2++) {
            int nb = 2 * kk2;
#pragma unroll
            for (int half = 0; half < 2; half++) {
                int src = nb + half;              // frag a{0,1} from nb, a{2,3} from nb+1
                float p0 = s[src][0], p1 = s[src][1], p2 = s[src][2], p3 = s[src][3];
                __nv_bfloat162 hA = __floats2bfloat162_rn(p0, p1);
                __nv_bfloat162 hB = __floats2bfloat162_rn(p2, p3);
                Ph[kk2][half * 2 + 0] = *(uint32_t*)&hA;
                Ph[kk2][half * 2 + 1] = *(uint32_t*)&hB;
                Pl[kk2][half * 2 + 0] = packbf(p0 - __bfloat162float(__low2bfloat16(hA)),
                                               p1 - __bfloat162float(__high2bfloat16(hA)));
                Pl[kk2][half * 2 + 1] = packbf(p2 - __bfloat162float(__low2bfloat16(hB)),
                                               p3 - __bfloat162float(__high2bfloat16(hB)));
            }
        }

        // ---- O += Ph*Vh + Ph*Vl + Pl*Vh ----
        for (int kk2 = 0; kk2 < 4; kk2++) {
#pragma unroll
            for (int dp = 0; dp < 8; dp++) {
                uint32_t voff = ((uint32_t)(kk2 * 16) + lrow) * 272u
                              + (uint32_t)dp * 32u + (uint32_t)(lane >> 4) * 16u;
                uint32_t h0, h1, h2, h3, l0r, l1r, l2r, l3r;
                ldmx4t(sVh + voff, h0, h1, h2, h3);
                ldmx4t(sVl + voff, l0r, l1r, l2r, l3r);
                int dnb = dp * 2;
                mma16816(oa[dnb][0], oa[dnb][1], oa[dnb][2], oa[dnb][3],
                         Ph[kk2][0], Ph[kk2][1], Ph[kk2][2], Ph[kk2][3], h0, h1);
                mma16816(oa[dnb][0], oa[dnb][1], oa[dnb][2], oa[dnb][3],
                         Ph[kk2][0], Ph[kk2][1], Ph[kk2][2], Ph[kk2][3], l0r, l1r);
                mma16816(oa[dnb][0], oa[dnb][1], oa[dnb][2], oa[dnb][3],
                         Pl[kk2][0], Pl[kk2][1], Pl[kk2][2], Pl[kk2][3], h0, h1);
                mma16816(oa[dnb + 1][0], oa[dnb + 1][1], oa[dnb + 1][2], oa[dnb + 1][3],
                         Ph[kk2][0], Ph[kk2][1], Ph[kk2][2], Ph[kk2][3], h2, h3);
                mma16816(oa[dnb + 1][0], oa[dnb + 1][1], oa[dnb + 1][2], oa[dnb + 1][3],
                         Ph[kk2][0], Ph[kk2][1], Ph[kk2][2], Ph[kk2][3], l2r, l3r);
                mma16816(oa[dnb + 1][0], oa[dnb + 1][1], oa[dnb + 1][2], oa[dnb + 1][3],
                         Pl[kk2][0], Pl[kk2][1], Pl[kk2][2], Pl[kk2][3], h2, h3);
            }
        }
        __syncthreads();
    }

    // ---- epilogue ----
    float inv0 = 1.0f / l0, inv1 = 1.0f / l1;
    int r0 = i0 + warp * 16 + g;
    float* ob = o + hoff;
#pragma unroll
    for (int dnb = 0; dnb < 16; dnb++) {
        int col = dnb * 8 + 2 * q4;
        float2 v0 = make_float2(oa[dnb][0] * inv0, oa[dnb][1] * inv0);
        float2 v1 = make_float2(oa[dnb][2] * inv1, oa[dnb][3] * inv1);
        *(float2*)&ob[(size_t)r0 * DMODEL + col]       = v0;
        *(float2*)&ob[(size_t)(r0 + 8) * DMODEL + col] = v1;
    }
}

// ---------------------------------------------------------------------------
extern "C" void kernel_launch(void* const* d_in, const int* in_sizes, int n_in,
                              void* d_out, int out_size)
{
    const float* x  = (const float*)d_in[0];
    const float* Wq = (const float*)d_in[1];
    const float* bq = (const float*)d_in[2];
    const float* Wk = (const float*)d_in[3];
    const float* bk = (const float*)d_in[4];
    const float* Wv = (const float*)d_in[5];
    const float* bv = (const float*)d_in[6];
    const float* Wo = (const float*)d_in[7];
    const float* bo = (const float*)d_in[8];
    float* out = (float*)d_out;

    float *qp, *kp, *vp, *ap;
    cudaGetSymbolAddress((void**)&qp, g_q);
    cudaGetSymbolAddress((void**)&kp, g_k);
    cudaGetSymbolAddress((void**)&vp, g_v);
    cudaGetSymbolAddress((void**)&ap, g_att);
    __nv_bfloat16 *xhi, *xlo, *ahi, *alo, *qhh, *qll, *khh, *kll, *vhh, *vll;
    __nv_bfloat16 *wqh, *wql, *wkh, *wkl, *wvh, *wvl, *woh, *wol;
    cudaGetSymbolAddress((void**)&xhi, g_xhi);
    cudaGetSymbolAddress((void**)&xlo, g_xlo);
    cudaGetSymbolAddress((void**)&ahi, g_ahi);
    cudaGetSymbolAddress((void**)&alo, g_alo);
    cudaGetSymbolAddress((void**)&qhh, g_qh);
    cudaGetSymbolAddress((void**)&qll, g_ql);
    cudaGetSymbolAddress((void**)&khh, g_kh);
    cudaGetSymbolAddress((void**)&kll, g_kl);
    cudaGetSymbolAddress((void**)&vhh, g_vh);
    cudaGetSymbolAddress((void**)&vll, g_vl);
    cudaGetSymbolAddress((void**)&wqh, g_wq_hi);
    cudaGetSymbolAddress((void**)&wql, g_wq_lo);
    cudaGetSymbolAddress((void**)&wkh, g_wk_hi);
    cudaGetSymbolAddress((void**)&wkl, g_wk_lo);
    cudaGetSymbolAddress((void**)&wvh, g_wv_hi);
    cudaGetSymbolAddress((void**)&wvl, g_wv_lo);
    cudaGetSymbolAddress((void**)&woh, g_wo_hi);
    cudaGetSymbolAddress((void**)&wol, g_wo_lo);

    cudaFuncSetAttribute(gemm_bf16x2, cudaFuncAttributeMaxDynamicSharedMemorySize, GEMM_SMEM);
    cudaFuncSetAttribute(flash_attn_mma, cudaFuncAttributeMaxDynamicSharedMemorySize, ATT_SMEM);

    // prep: split x, transpose+split weights
    int n4x = ROWS * DMODEL / 4;
    split_kernel<<<(n4x + 255) / 256, 256>>>((const float4*)x, xhi, xlo, n4x);
    dim3 tgrid(DMODEL / 32, DMODEL / 32);
    transpose_split<<<tgrid, 256>>>(Wq, wqh, wql);
    transpose_split<<<tgrid, 256>>>(Wk, wkh, wkl);
    transpose_split<<<tgrid, 256>>>(Wv, wvh, wvl);
    transpose_split<<<tgrid, 256>>>(Wo, woh, wol);

    // QKV projections on tensor cores
    dim3 ggrid(DMODEL / TN, ROWS / TM);   // (16, 32)
    gemm_bf16x2<<<ggrid, 256, GEMM_SMEM>>>(xhi, xlo, wqh, wql, bq, qp);
    gemm_bf16x2<<<ggrid, 256, GEMM_SMEM>>>(xhi, xlo, wkh, wkl, bk, kp);
    gemm_bf16x2<<<ggrid, 256, GEMM_SMEM>>>(xhi, xlo, wvh, wvl, bv, vp);

    // rotary (+scale) + split q,k; split v
    const int PAIRS = ROWS * HEADS * 64;
    rotary_split<<<(PAIRS + 255) / 256, 256>>>(qp, kp, qhh, qll, khh, kll);
    split_kernel<<<(n4x + 255) / 256, 256>>>((const float4*)vp, vhh, vll, n4x);

    // tensor-core flash attention
    dim3 attn_grid(NSEQ / 64, BATCH * HEADS);   // (32, 32)
    flash_attn_mma<<<attn_grid, 128, ATT_SMEM>>>(qhh, qll, khh, kll, vhh, vll, ap);

    // output projection
    split_kernel<<<(n4x + 255) / 256, 256>>>((const float4*)ap, ahi, alo, n4x);
    gemm_bf16x2<<<ggrid, 256, GEMM_SMEM>>>(ahi, alo, woh, wol, bo, out);
}

// round 5
// speedup vs baseline: 3.6060x; 1.0715x over previous
#include <cuda_runtime.h>
#include <cuda_bf16.h>
#include <math.h>
#include <stdint.h>

#define BATCH 2
#define NSEQ  2048
#define DMODEL 2048
#define HEADS 16
#define DHEAD 128
#define ROWS (BATCH*NSEQ)   // 4096

// ---------------------------------------------------------------------------
// scratch (device globals: no allocation allowed)
// ---------------------------------------------------------------------------
__device__ __nv_bfloat16 g_xhi[ROWS*DMODEL];
__device__ __nv_bfloat16 g_xlo[ROWS*DMODEL];
__device__ __nv_bfloat16 g_ahi[ROWS*DMODEL];
__device__ __nv_bfloat16 g_alo[ROWS*DMODEL];
__device__ __nv_bfloat16 g_qh[ROWS*DMODEL];
__device__ __nv_bfloat16 g_ql[ROWS*DMODEL];
__device__ __nv_bfloat16 g_kh[ROWS*DMODEL];
__device__ __nv_bfloat16 g_kl[ROWS*DMODEL];
__device__ __nv_bfloat16 g_vh[ROWS*DMODEL];
__device__ __nv_bfloat16 g_vl[ROWS*DMODEL];
__device__ __nv_bfloat16 g_wq_hi[DMODEL*DMODEL];
__device__ __nv_bfloat16 g_wq_lo[DMODEL*DMODEL];
__device__ __nv_bfloat16 g_wk_hi[DMODEL*DMODEL];
__device__ __nv_bfloat16 g_wk_lo[DMODEL*DMODEL];
__device__ __nv_bfloat16 g_wv_hi[DMODEL*DMODEL];
__device__ __nv_bfloat16 g_wv_lo[DMODEL*DMODEL];
__device__ __nv_bfloat16 g_wo_hi[DMODEL*DMODEL];
__device__ __nv_bfloat16 g_wo_lo[DMODEL*DMODEL];

// ---------------------------------------------------------------------------
// helpers
// ---------------------------------------------------------------------------
__device__ __forceinline__ uint32_t smem_u32(const void* p) {
    uint32_t a;
    asm("{ .reg .u64 t; cvta.to.shared.u64 t, %1; cvt.u32.u64 %0, t; }" : "=r"(a) : "l"(p));
    return a;
}

__device__ __forceinline__ void cp16(uint32_t dst, const void* src) {
    asm volatile("cp.async.cg.shared.global [%0], [%1], 16;" :: "r"(dst), "l"(src));
}
#define CP_COMMIT() asm volatile("cp.async.commit_group;" ::: "memory")
#define CP_WAIT(n)  asm volatile("cp.async.wait_group %0;" :: "n"(n) : "memory")

__device__ __forceinline__ void ldmx4(uint32_t addr, uint32_t& r0, uint32_t& r1,
                                      uint32_t& r2, uint32_t& r3) {
    asm volatile("ldmatrix.sync.aligned.m8n8.x4.shared.b16 {%0,%1,%2,%3}, [%4];"
                 : "=r"(r0), "=r"(r1), "=r"(r2), "=r"(r3) : "r"(addr));
}
__device__ __forceinline__ void ldmx4t(uint32_t addr, uint32_t& r0, uint32_t& r1,
                                       uint32_t& r2, uint32_t& r3) {
    asm volatile("ldmatrix.sync.aligned.m8n8.x4.trans.shared.b16 {%0,%1,%2,%3}, [%4];"
                 : "=r"(r0), "=r"(r1), "=r"(r2), "=r"(r3) : "r"(addr));
}

__device__ __forceinline__ void mma16816(float& c0, float& c1, float& c2, float& c3,
                                         uint32_t a0, uint32_t a1, uint32_t a2, uint32_t a3,
                                         uint32_t b0, uint32_t b1) {
    asm volatile(
        "mma.sync.aligned.m16n8k16.row.col.f32.bf16.bf16.f32 "
        "{%0,%1,%2,%3}, {%4,%5,%6,%7}, {%8,%9}, {%0,%1,%2,%3};"
        : "+f"(c0), "+f"(c1), "+f"(c2), "+f"(c3)
        : "r"(a0), "r"(a1), "r"(a2), "r"(a3), "r"(b0), "r"(b1));
}

__device__ __forceinline__ uint32_t packbf(float a, float b) {
    __nv_bfloat162 t = __floats2bfloat162_rn(a, b);
    return *(uint32_t*)&t;
}

// ---------------------------------------------------------------------------
// split: fp32 -> (hi, lo) bf16 pair
// ---------------------------------------------------------------------------
__global__ __launch_bounds__(256)
void split_kernel(const float4* __restrict__ in, __nv_bfloat16* __restrict__ hi,
                  __nv_bfloat16* __restrict__ lo, int n4)
{
    int i = blockIdx.x * 256 + threadIdx.x;
    if (i >= n4) return;
    float4 v = in[i];
    __nv_bfloat16 h0 = __float2bfloat16(v.x);
    __nv_bfloat16 h1 = __float2bfloat16(v.y);
    __nv_bfloat16 h2 = __float2bfloat16(v.z);
    __nv_bfloat16 h3 = __float2bfloat16(v.w);
    __nv_bfloat162* hp = (__nv_bfloat162*)(hi + 4 * (size_t)i);
    hp[0] = __nv_bfloat162(h0, h1);
    hp[1] = __nv_bfloat162(h2, h3);
    __nv_bfloat162* lp = (__nv_bfloat162*)(lo + 4 * (size_t)i);
    lp[0] = __nv_bfloat162(__float2bfloat16(v.x - __bfloat162float(h0)),
                           __float2bfloat16(v.y - __bfloat162float(h1)));
    lp[1] = __nv_bfloat162(__float2bfloat16(v.z - __bfloat162float(h2)),
                           __float2bfloat16(v.w - __bfloat162float(h3)));
}

// ---------------------------------------------------------------------------
// transpose + split: W[K][N] fp32 -> Wt[N][K] bf16 (hi, lo)
// ---------------------------------------------------------------------------
__global__ __launch_bounds__(256)
void transpose_split(const float* __restrict__ W, __nv_bfloat16* __restrict__ th,
                     __nv_bfloat16* __restrict__ tl)
{
    __shared__ float t[32][33];
    int n0 = blockIdx.x * 32, k0 = blockIdx.y * 32;
    int tx = threadIdx.x & 31, ty = threadIdx.x >> 5;   // 32 x 8
#pragma unroll
    for (int i = 0; i < 32; i += 8)
        t[ty + i][tx] = W[(size_t)(k0 + ty + i) * DMODEL + n0 + tx];
    __syncthreads();
#pragma unroll
    for (int i = 0; i < 32; i += 8) {
        float v = t[tx][ty + i];
        __nv_bfloat16 h = __float2bfloat16(v);
        size_t o = (size_t)(n0 + ty + i) * DMODEL + k0 + tx;
        th[o] = h;
        tl[o] = __float2bfloat16(v - __bfloat162float(h));
    }
}

// ---------------------------------------------------------------------------
// GEMM tiles / pipeline config
// ---------------------------------------------------------------------------
#define GK DMODEL
#define TM 128
#define TN 128
#define KC 32
#define RSTR 40
#define TILE_B (128u * RSTR * 2u)
#define STAGE_B (4u * TILE_B)
#define GEMM_SMEM (2u * STAGE_B)     // 81920 B (also holds 128x132 fp32 epilogue tile)

// ---------------------------------------------------------------------------
// Fused QKV GEMM: C = x @ W{q,k,v} + b, then rotary(+scale) and bf16 hi/lo
// split fused in the epilogue. grid (48, 32): blockIdx.x selects matrix
// (x/16) and head-column (x%16). One CTA column tile == one head.
// ---------------------------------------------------------------------------
__global__ __launch_bounds__(256)
void gemm_qkv(const __nv_bfloat16* __restrict__ xhi, const __nv_bfloat16* __restrict__ xlo,
              const __nv_bfloat16* __restrict__ wqh, const __nv_bfloat16* __restrict__ wql,
              const __nv_bfloat16* __restrict__ wkh, const __nv_bfloat16* __restrict__ wkl,
              const __nv_bfloat16* __restrict__ wvh, const __nv_bfloat16* __restrict__ wvl,
              const float* __restrict__ bq, const float* __restrict__ bk,
              const float* __restrict__ bv,
              __nv_bfloat16* __restrict__ qh, __nv_bfloat16* __restrict__ ql,
              __nv_bfloat16* __restrict__ kh, __nv_bfloat16* __restrict__ kl,
              __nv_bfloat16* __restrict__ vh, __nv_bfloat16* __restrict__ vl)
{
    extern __shared__ __align__(128) char smem[];
    uint32_t sb = smem_u32(smem);
    const int tid  = threadIdx.x;
    const int wid  = tid >> 5;
    const int lane = tid & 31;
    const int brow = blockIdx.y * TM;
    const int mtx  = blockIdx.x >> 4;            // 0=q, 1=k, 2=v
    const int bcol = (blockIdx.x & 15) * TN;     // column within [0, 2048)

    const __nv_bfloat16* Bhi = (mtx == 0) ? wqh : (mtx == 1) ? wkh : wvh;
    const __nv_bfloat16* Blo = (mtx == 0) ? wql : (mtx == 1) ? wkl : wvl;
    const float* bias        = (mtx == 0) ? bq  : (mtx == 1) ? bk  : bv;
    __nv_bfloat16* Oh        = (mtx == 0) ? qh  : (mtx == 1) ? kh  : vh;
    __nv_bfloat16* Ol        = (mtx == 0) ? ql  : (mtx == 1) ? kl  : vl;

    const int wm = wid & 1;
    const int wn = wid >> 1;

    float acc[4][4][4];
#pragma unroll
    for (int i = 0; i < 4; i++)
#pragma unroll
        for (int j = 0; j < 4; j++)
#pragma unroll
            for (int r = 0; r < 4; r++) acc[i][j][r] = 0.f;

    auto copy_chunk = [&](int c, int stg) {
        int k0 = c * KC;
        uint32_t base = sb + (uint32_t)stg * STAGE_B;
        const __nv_bfloat16* srcs[4] = { xhi, xlo, Bhi, Blo };
        int rows0[4] = { brow, brow, bcol, bcol };
#pragma unroll
        for (int t = 0; t < 4; t++) {
            const __nv_bfloat16* src = srcs[t] + (size_t)rows0[t] * GK + k0;
            uint32_t tb = base + (uint32_t)t * TILE_B;
#pragma unroll
            for (int i = 0; i < 2; i++) {
                int s = i * 256 + tid;
                int r = s >> 2, seg = s & 3;
                cp16(tb + (uint32_t)r * (RSTR * 2) + (uint32_t)seg * 16u,
                     src + (size_t)r * GK + seg * 8);
            }
        }
        CP_COMMIT();
    };

    const int NCH = GK / KC;
    copy_chunk(0, 0);

    const uint32_t lrow = (uint32_t)(lane & 15);
    const uint32_t lcol = (uint32_t)((lane >> 4) & 1) * 8u;

    for (int c = 0; c < NCH; c++) {
        int stg = c & 1;
        if (c + 1 < NCH) {
            copy_chunk(c + 1, stg ^ 1);
            CP_WAIT(1);
        } else {
            CP_WAIT(0);
        }
        __syncthreads();

        uint32_t base = sb + (uint32_t)stg * STAGE_B;
        uint32_t ah_b = base;
        uint32_t al_b = base + TILE_B;
        uint32_t bh_b = base + 2u * TILE_B;
        uint32_t bl_b = base + 3u * TILE_B;

#pragma unroll
        for (int kk = 0; kk < 2; kk++) {
            uint32_t koff = (uint32_t)(kk * 16) * 2u + lcol * 2u;

            uint32_t Ah[4][4], Al[4][4];
#pragma unroll
            for (int mi = 0; mi < 4; mi++) {
                uint32_t roff = ((uint32_t)(wm * 64 + mi * 16) + lrow) * (RSTR * 2u) + koff;
                ldmx4(ah_b + roff, Ah[mi][0], Ah[mi][1], Ah[mi][2], Ah[mi][3]);
                ldmx4(al_b + roff, Al[mi][0], Al[mi][1], Al[mi][2], Al[mi][3]);
            }
            uint32_t Bh[4][2], Bl[4][2];
#pragma unroll
            for (int np = 0; np < 2; np++) {
                uint32_t roff = ((uint32_t)(wn * 32 + np * 16) + lrow) * (RSTR * 2u) + koff;
                uint32_t r0, r1, r2, r3;
                ldmx4(bh_b + roff, r0, r1, r2, r3);
                Bh[np * 2][0] = r0; Bh[np * 2 + 1][0] = r1;
                Bh[np * 2][1] = r2; Bh[np * 2 + 1][1] = r3;
                ldmx4(bl_b + roff, r0, r1, r2, r3);
                Bl[np * 2][0] = r0; Bl[np * 2 + 1][0] = r1;
                Bl[np * 2][1] = r2; Bl[np * 2 + 1][1] = r3;
            }

#pragma unroll
            for (int mi = 0; mi < 4; mi++)
#pragma unroll
                for (int ni = 0; ni < 4; ni++) {
                    mma16816(acc[mi][ni][0], acc[mi][ni][1], acc[mi][ni][2], acc[mi][ni][3],
                             Ah[mi][0], Ah[mi][1], Ah[mi][2], Ah[mi][3],
                             Bh[ni][0], Bh[ni][1]);
                    mma16816(acc[mi][ni][0], acc[mi][ni][1], acc[mi][ni][2], acc[mi][ni][3],
                             Ah[mi][0], Ah[mi][1], Ah[mi][2], Ah[mi][3],
                             Bl[ni][0], Bl[ni][1]);
                    mma16816(acc[mi][ni][0], acc[mi][ni][1], acc[mi][ni][2], acc[mi][ni][3],
                             Al[mi][0], Al[mi][1], Al[mi][2], Al[mi][3],
                             Bh[ni][0], Bh[ni][1]);
                }
        }
        __syncthreads();
    }

    // ------ fused epilogue: stage fp32 tile in smem, rotary+split, store ----
    float* ft = (float*)smem;    // [128][132] fp32 = 67584 B (stage bufs free)
    int g = lane >> 2, t4 = lane & 3;
#pragma unroll
    for (int mi = 0; mi < 4; mi++) {
        int r0 = wm * 64 + mi * 16 + g;
#pragma unroll
        for (int ni = 0; ni < 4; ni++) {
            int cl = wn * 32 + ni * 8 + 2 * t4;
            float2 b01 = *(const float2*)&bias[bcol + cl];
            *(float2*)&ft[r0 * 132 + cl] =
                make_float2(acc[mi][ni][0] + b01.x, acc[mi][ni][1] + b01.y);
            *(float2*)&ft[(r0 + 8) * 132 + cl] =
                make_float2(acc[mi][ni][2] + b01.x, acc[mi][ni][3] + b01.y);
        }
    }
    __syncthreads();

    const bool  do_rot = (mtx < 2);
    const float scale  = (mtx == 0) ? 0.08838834764831845f : 1.0f;
    int d  = tid & 63;
    int rb = tid >> 6;
    float inv_freq = __expf(-(float)d * (9.210340371976184f / 64.0f));

    for (int rr = rb; rr < 128; rr += 4) {
        int grow = brow + rr;
        float a = ft[rr * 132 + d];
        float b2 = ft[rr * 132 + d + 64];
        float oa, ob2;
        if (do_rot) {
            int n = grow & (NSEQ - 1);
            float s, c;
            sincosf((float)n * inv_freq, &s, &c);
            oa  = (a * c - b2 * s) * scale;
            ob2 = (b2 * c + a * s) * scale;
        } else {
            oa = a; ob2 = b2;
        }
        size_t base = (size_t)grow * DMODEL + bcol + d;
        __nv_bfloat16 h = __float2bfloat16(oa);
        Oh[base] = h;
        Ol[base] = __float2bfloat16(oa - __bfloat162float(h));
        h = __float2bfloat16(ob2);
        Oh[base + 64] = h;
        Ol[base + 64] = __float2bfloat16(ob2 - __bfloat162float(h));
    }
}

// ---------------------------------------------------------------------------
// GEMM (3-pass split bf16) with fp32 output + bias — used for out projection
// ---------------------------------------------------------------------------
__global__ __launch_bounds__(256)
void gemm_bf16x2(const __nv_bfloat16* __restrict__ Ahi, const __nv_bfloat16* __restrict__ Alo,
                 const __nv_bfloat16* __restrict__ Bhi, const __nv_bfloat16* __restrict__ Blo,
                 const float* __restrict__ bias, float* __restrict__ C)
{
    extern __shared__ __align__(128) char smem[];
    uint32_t sb = smem_u32(smem);
    const int tid  = threadIdx.x;
    const int wid  = tid >> 5;
    const int lane = tid & 31;
    const int brow = blockIdx.y * TM;
    const int bcol = blockIdx.x * TN;

    const int wm = wid & 1;
    const int wn = wid >> 1;

    float acc[4][4][4];
#pragma unroll
    for (int i = 0; i < 4; i++)
#pragma unroll
        for (int j = 0; j < 4; j++)
#pragma unroll
            for (int r = 0; r < 4; r++) acc[i][j][r] = 0.f;

    auto copy_chunk = [&](int c, int stg) {
        int k0 = c * KC;
        uint32_t base = sb + (uint32_t)stg * STAGE_B;
        const __nv_bfloat16* srcs[4] = { Ahi, Alo, Bhi, Blo };
        int rows0[4] = { brow, brow, bcol, bcol };
#pragma unroll
        for (int t = 0; t < 4; t++) {
            const __nv_bfloat16* src = srcs[t] + (size_t)rows0[t] * GK + k0;
            uint32_t tb = base + (uint32_t)t * TILE_B;
#pragma unroll
            for (int i = 0; i < 2; i++) {
                int s = i * 256 + tid;
                int r = s >> 2, seg = s & 3;
                cp16(tb + (uint32_t)r * (RSTR * 2) + (uint32_t)seg * 16u,
                     src + (size_t)r * GK + seg * 8);
            }
        }
        CP_COMMIT();
    };

    const int NCH = GK / KC;
    copy_chunk(0, 0);

    const uint32_t lrow = (uint32_t)(lane & 15);
    const uint32_t lcol = (uint32_t)((lane >> 4) & 1) * 8u;

    for (int c = 0; c < NCH; c++) {
        int stg = c & 1;
        if (c + 1 < NCH) {
            copy_chunk(c + 1, stg ^ 1);
            CP_WAIT(1);
        } else {
            CP_WAIT(0);
        }
        __syncthreads();

        uint32_t base = sb + (uint32_t)stg * STAGE_B;
        uint32_t ah_b = base;
        uint32_t al_b = base + TILE_B;
        uint32_t bh_b = base + 2u * TILE_B;
        uint32_t bl_b = base + 3u * TILE_B;

#pragma unroll
        for (int kk = 0; kk < 2; kk++) {
            uint32_t koff = (uint32_t)(kk * 16) * 2u + lcol * 2u;

            uint32_t Ah[4][4], Al[4][4];
#pragma unroll
            for (int mi = 0; mi < 4; mi++) {
                uint32_t roff = ((uint32_t)(wm * 64 + mi * 16) + lrow) * (RSTR * 2u) + koff;
                ldmx4(ah_b + roff, Ah[mi][0], Ah[mi][1], Ah[mi][2], Ah[mi][3]);
                ldmx4(al_b + roff, Al[mi][0], Al[mi][1], Al[mi][2], Al[mi][3]);
            }
            uint32_t Bh[4][2], Bl[4][2];
#pragma unroll
            for (int np = 0; np < 2; np++) {
                uint32_t roff = ((uint32_t)(wn * 32 + np * 16) + lrow) * (RSTR * 2u) + koff;
                uint32_t r0, r1, r2, r3;
                ldmx4(bh_b + roff, r0, r1, r2, r3);
                Bh[np * 2][0] = r0; Bh[np * 2 + 1][0] = r1;
                Bh[np * 2][1] = r2; Bh[np * 2 + 1][1] = r3;
                ldmx4(bl_b + roff, r0, r1, r2, r3);
                Bl[np * 2][0] = r0; Bl[np * 2 + 1][0] = r1;
                Bl[np * 2][1] = r2; Bl[np * 2 + 1][1] = r3;
            }

#pragma unroll
            for (int mi = 0; mi < 4; mi++)
#pragma unroll
                for (int ni = 0; ni < 4; ni++) {
                    mma16816(acc[mi][ni][0], acc[mi][ni][1], acc[mi][ni][2], acc[mi][ni][3],
                             Ah[mi][0], Ah[mi][1], Ah[mi][2], Ah[mi][3],
                             Bh[ni][0], Bh[ni][1]);
                    mma16816(acc[mi][ni][0], acc[mi][ni][1], acc[mi][ni][2], acc[mi][ni][3],
                             Ah[mi][0], Ah[mi][1], Ah[mi][2], Ah[mi][3],
                             Bl[ni][0], Bl[ni][1]);
                    mma16816(acc[mi][ni][0], acc[mi][ni][1], acc[mi][ni][2], acc[mi][ni][3],
                             Al[mi][0], Al[mi][1], Al[mi][2], Al[mi][3],
                             Bh[ni][0], Bh[ni][1]);
                }
        }
        __syncthreads();
    }

    int g = lane >> 2, t4 = lane & 3;
#pragma unroll
    for (int mi = 0; mi < 4; mi++) {
        int r0 = brow + wm * 64 + mi * 16 + g;
#pragma unroll
        for (int ni = 0; ni < 4; ni++) {
            int col = bcol + wn * 32 + ni * 8 + 2 * t4;
            float2 b01 = *(const float2*)&bias[col];
            float2 o0, o1;
            o0.x = acc[mi][ni][0] + b01.x;
            o0.y = acc[mi][ni][1] + b01.y;
            o1.x = acc[mi][ni][2] + b01.x;
            o1.y = acc[mi][ni][3] + b01.y;
            *(float2*)&C[(size_t)r0 * DMODEL + col]       = o0;
            *(float2*)&C[(size_t)(r0 + 8) * DMODEL + col] = o1;
        }
    }
}

// ---------------------------------------------------------------------------
// Flash attention (causal) with mma.sync, split-bf16 (3 passes each mma).
// BR=BC=64, 128 threads (4 warps x 16 q-rows). Epilogue emits bf16 hi/lo.
// ---------------------------------------------------------------------------
#define ASTR 136                        // bf16 elems per smem row (272B)
#define ATILE_B (64u * ASTR * 2u)       // 17408 B
#define ATT_SMEM (6u * ATILE_B)         // 104448 B

__global__ __launch_bounds__(128)
void flash_attn_mma(const __nv_bfloat16* __restrict__ qh, const __nv_bfloat16* __restrict__ ql,
                    const __nv_bfloat16* __restrict__ kh, const __nv_bfloat16* __restrict__ kl,
                    const __nv_bfloat16* __restrict__ vh, const __nv_bfloat16* __restrict__ vl,
                    __nv_bfloat16* __restrict__ oh, __nv_bfloat16* __restrict__ ol)
{
    extern __shared__ __align__(128) char smem[];
    uint32_t sb = smem_u32(smem);
    uint32_t sQh = sb, sQl = sb + ATILE_B;
    uint32_t sKh = sb + 2u * ATILE_B, sKl = sb + 3u * ATILE_B;
    uint32_t sVh = sb + 4u * ATILE_B, sVl = sb + 5u * ATILE_B;

    const int tid  = threadIdx.x;
    const int warp = tid >> 5;
    const int lane = tid & 31;
    const int g    = lane >> 2;
    const int q4   = lane & 3;

    const int it = gridDim.x - 1 - blockIdx.x;   // heavy tiles first
    const int bh = blockIdx.y;
    const int b = bh >> 4, h = bh & 15;
    const int i0 = it * 64;

    const size_t hoff = (size_t)b * NSEQ * DMODEL + h * DHEAD;
    const __nv_bfloat16* qhb = qh + hoff;
    const __nv_bfloat16* qlb = ql + hoff;
    const __nv_bfloat16* khb = kh + hoff;
    const __nv_bfloat16* klb = kl + hoff;
    const __nv_bfloat16* vhb = vh + hoff;
    const __nv_bfloat16* vlb = vl + hoff;

    // preload Q hi/lo
    {
        const __nv_bfloat16* srcs[2] = { qhb, qlb };
        uint32_t dsts[2] = { sQh, sQl };
#pragma unroll
        for (int t = 0; t < 2; t++)
#pragma unroll
            for (int i = 0; i < 8; i++) {
                int s = i * 128 + tid;
                int r = s >> 4, seg = s & 15;
                cp16(dsts[t] + (uint32_t)r * 272u + (uint32_t)seg * 16u,
                     srcs[t] + (size_t)(i0 + r) * DMODEL + seg * 8);
            }
        CP_COMMIT();
    }

    float m0 = -1e30f, m1 = -1e30f, l0 = 0.f, l1 = 0.f;
    float oa[16][4];
#pragma unroll
    for (int d = 0; d < 16; d++)
#pragma unroll
        for (int r = 0; r < 4; r++) oa[d][r] = 0.f;

    const uint32_t lrow = (uint32_t)(lane & 15);
    const uint32_t lseg16 = (uint32_t)(lane >> 4) * 16u;

    for (int jt = 0; jt <= it; jt++) {
        int j0 = jt * 64;
        {
            const __nv_bfloat16* srcs[4] = { khb, klb, vhb, vlb };
            uint32_t dsts[4] = { sKh, sKl, sVh, sVl };
#pragma unroll
            for (int t = 0; t < 4; t++)
#pragma unroll
                for (int i = 0; i < 8; i++) {
                    int s = i * 128 + tid;
                    int r = s >> 4, seg = s & 15;
                    cp16(dsts[t] + (uint32_t)r * 272u + (uint32_t)seg * 16u,
                         srcs[t] + (size_t)(j0 + r) * DMODEL + seg * 8);
                }
            CP_COMMIT();
        }
        CP_WAIT(0);
        __syncthreads();

        // ---- S = Qh*Kh + Qh*Kl + Ql*Kh ----
        float s[8][4];
#pragma unroll
        for (int nb = 0; nb < 8; nb++)
#pragma unroll
            for (int r = 0; r < 4; r++) s[nb][r] = 0.f;

        for (int kk = 0; kk < 8; kk++) {
            uint32_t qoff = ((uint32_t)(warp * 16) + lrow) * 272u + lseg16 + (uint32_t)kk * 32u;
            uint32_t Qh4[4], Ql4[4];
            ldmx4(sQh + qoff, Qh4[0], Qh4[1], Qh4[2], Qh4[3]);
            ldmx4(sQl + qoff, Ql4[0], Ql4[1], Ql4[2], Ql4[3]);
#pragma unroll
            for (int np = 0; np < 4; np++) {
                uint32_t koff = ((uint32_t)(np * 16) + lrow) * 272u + lseg16 + (uint32_t)kk * 32u;
                uint32_t h0, h1, h2, h3, l0r, l1r, l2r, l3r;
                ldmx4(sKh + koff, h0, h1, h2, h3);
                ldmx4(sKl + koff, l0r, l1r, l2r, l3r);
                int nb = np * 2;
                mma16816(s[nb][0], s[nb][1], s[nb][2], s[nb][3],
                         Qh4[0], Qh4[1], Qh4[2], Qh4[3], h0, h2);
                mma16816(s[nb][0], s[nb][1], s[nb][2], s[nb][3],
                         Qh4[0], Qh4[1], Qh4[2], Qh4[3], l0r, l2r);
                mma16816(s[nb][0], s[nb][1], s[nb][2], s[nb][3],
                         Ql4[0], Ql4[1], Ql4[2], Ql4[3], h0, h2);
                mma16816(s[nb + 1][0], s[nb + 1][1], s[nb + 1][2], s[nb + 1][3],
                         Qh4[0], Qh4[1], Qh4[2], Qh4[3], h1, h3);
                mma16816(s[nb + 1][0], s[nb + 1][1], s[nb + 1][2], s[nb + 1][3],
                         Qh4[0], Qh4[1], Qh4[2], Qh4[3], l1r, l3r);
                mma16816(s[nb + 1][0], s[nb + 1][1], s[nb + 1][2], s[nb + 1][3],
                         Ql4[0], Ql4[1], Ql4[2], Ql4[3], h1, h3);
            }
        }

        if (jt == it) {
            int r0 = warp * 16 + g;
            int r1 = r0 + 8;
#pragma unroll
            for (int nb = 0; nb < 8; nb++) {
                int c0 = nb * 8 + 2 * q4;
                if (c0 > r0)     s[nb][0] = -1e30f;
                if (c0 + 1 > r0) s[nb][1] = -1e30f;
                if (c0 > r1)     s[nb][2] = -1e30f;
                if (c0 + 1 > r1) s[nb][3] = -1e30f;
            }
        }

        float mx0 = -1e30f, mx1 = -1e30f;
#pragma unroll
        for (int nb = 0; nb < 8; nb++) {
            mx0 = fmaxf(mx0, fmaxf(s[nb][0], s[nb][1]));
            mx1 = fmaxf(mx1, fmaxf(s[nb][2], s[nb][3]));
        }
        mx0 = fmaxf(mx0, __shfl_xor_sync(0xffffffffu, mx0, 1));
        mx0 = fmaxf(mx0, __shfl_xor_sync(0xffffffffu, mx0, 2));
        mx1 = fmaxf(mx1, __shfl_xor_sync(0xffffffffu, mx1, 1));
        mx1 = fmaxf(mx1, __shfl_xor_sync(0xffffffffu, mx1, 2));

        float m0n = fmaxf(m0, mx0), m1n = fmaxf(m1, mx1);
        float f0 = __expf(m0 - m0n), f1 = __expf(m1 - m1n);

        float sum0 = 0.f, sum1 = 0.f;
#pragma unroll
        for (int nb = 0; nb < 8; nb++) {
            s[nb][0] = __expf(s[nb][0] - m0n);
            s[nb][1] = __expf(s[nb][1] - m0n);
            s[nb][2] = __expf(s[nb][2] - m1n);
            s[nb][3] = __expf(s[nb][3] - m1n);
            sum0 += s[nb][0] + s[nb][1];
            sum1 += s[nb][2] + s[nb][3];
        }
        sum0 += __shfl_xor_sync(0xffffffffu, sum0, 1);
        sum0 += __shfl_xor_sync(0xffffffffu, sum0, 2);
        sum1 += __shfl_xor_sync(0xffffffffu, sum1, 1);
        sum1 += __shfl_xor_sync(0xffffffffu, sum1, 2);

        m0 = m0n; m1 = m1n;
        l0 = l0 * f0 + sum0;
        l1 = l1 * f1 + sum1;

#pragma unroll
        for (int d = 0; d < 16; d++) {
            oa[d][0] *= f0; oa[d][1] *= f0;
            oa[d][2] *= f1; oa[d][3] *= f1;
        }

        uint32_t Ph[4][4], Pl[4][4];
#pragma unroll
        for (int kk2 = 0; kk2 < 4; kk2++) {
            int nb = 2 * kk2;
#pragma unroll
            for (int half = 0; half < 2; half++) {
                int src = nb + half;
                float p0 = s[src][0], p1 = s[src][1], p2 = s[src][2], p3 = s[src][3];
                __nv_bfloat162 hA = __floats2bfloat162_rn(p0, p1);
                __nv_bfloat162 hB = __floats2bfloat162_rn(p2, p3);
                Ph[kk2][half * 2 + 0] = *(uint32_t*)&hA;
                Ph[kk2][half * 2 + 1] = *(uint32_t*)&hB;
                Pl[kk2][half * 2 + 0] = packbf(p0 - __bfloat162float(__low2bfloat16(hA)),
                                               p1 - __bfloat162float(__high2bfloat16(hA)));
                Pl[kk2][half * 2 + 1] = packbf(p2 - __bfloat162float(__low2bfloat16(hB)),
                                               p3 - __bfloat162float(__high2bfloat16(hB)));
            }
        }

        for (int kk2 = 0; kk2 < 4; kk2++) {
#pragma unroll
            for (int dp = 0; dp < 8; dp++) {
                uint32_t voff = ((uint32_t)(kk2 * 16) + lrow) * 272u
                              + (uint32_t)dp * 32u + (uint32_t)(lane >> 4) * 16u;
                uint32_t h0, h1, h2, h3, l0r, l1r, l2r, l3r;
                ldmx4t(sVh + voff, h0, h1, h2, h3);
                ldmx4t(sVl + voff, l0r, l1r, l2r, l3r);
                int dnb = dp * 2;
                mma16816(oa[dnb][0], oa[dnb][1], oa[dnb][2], oa[dnb][3],
                         Ph[kk2][0], Ph[kk2][1], Ph[kk2][2], Ph[kk2][3], h0, h1);
                mma16816(oa[dnb][0], oa[dnb][1], oa[dnb][2], oa[dnb][3],
                         Ph[kk2][0], Ph[kk2][1], Ph[kk2][2], Ph[kk2][3], l0r, l1r);
                mma16816(oa[dnb][0], oa[dnb][1], oa[dnb][2], oa[dnb][3],
                         Pl[kk2][0], Pl[kk2][1], Pl[kk2][2], Pl[kk2][3], h0, h1);
                mma16816(oa[dnb + 1][0], oa[dnb + 1][1], oa[dnb + 1][2], oa[dnb + 1][3],
                         Ph[kk2][0], Ph[kk2][1], Ph[kk2][2], Ph[kk2][3], h2, h3);
                mma16816(oa[dnb + 1][0], oa[dnb + 1][1], oa[dnb + 1][2], oa[dnb + 1][3],
                         Ph[kk2][0], Ph[kk2][1], Ph[kk2][2], Ph[kk2][3], l2r, l3r);
                mma16816(oa[dnb + 1][0], oa[dnb + 1][1], oa[dnb + 1][2], oa[dnb + 1][3],
                         Pl[kk2][0], Pl[kk2][1], Pl[kk2][2], Pl[kk2][3], h2, h3);
            }
        }
        __syncthreads();
    }

    // ---- epilogue: normalize, split to bf16 hi/lo ----
    float inv0 = 1.0f / l0, inv1 = 1.0f / l1;
    int r0 = i0 + warp * 16 + g;
    __nv_bfloat16* ohb = oh + hoff;
    __nv_bfloat16* olb = ol + hoff;
#pragma unroll
    for (int dnb = 0; dnb < 16; dnb++) {
        int col = dnb * 8 + 2 * q4;
        float a0 = oa[dnb][0] * inv0, a1 = oa[dnb][1] * inv0;
        float b0 = oa[dnb][2] * inv1, b1 = oa[dnb][3] * inv1;
        __nv_bfloat162 h0 = __floats2bfloat162_rn(a0, a1);
        __nv_bfloat162 h1 = __floats2bfloat162_rn(b0, b1);
        *(__nv_bfloat162*)&ohb[(size_t)r0 * DMODEL + col] = h0;
        *(__nv_bfloat162*)&ohb[(size_t)(r0 + 8) * DMODEL + col] = h1;
        __nv_bfloat162 lo0, lo1;
        lo0 = __floats2bfloat162_rn(a0 - __bfloat162float(__low2bfloat16(h0)),
                                    a1 - __bfloat162float(__high2bfloat16(h0)));
        lo1 = __floats2bfloat162_rn(b0 - __bfloat162float(__low2bfloat16(h1)),
                                    b1 - __bfloat162float(__high2bfloat16(h1)));
        *(__nv_bfloat162*)&olb[(size_t)r0 * DMODEL + col] = lo0;
        *(__nv_bfloat162*)&olb[(size_t)(r0 + 8) * DMODEL + col] = lo1;
    }
}

// ---------------------------------------------------------------------------
extern "C" void kernel_launch(void* const* d_in, const int* in_sizes, int n_in,
                              void* d_out, int out_size)
{
    const float* x  = (const float*)d_in[0];
    const float* Wq = (const float*)d_in[1];
    const float* bq = (const float*)d_in[2];
    const float* Wk = (const float*)d_in[3];
    const float* bk = (const float*)d_in[4];
    const float* Wv = (const float*)d_in[5];
    const float* bv = (const float*)d_in[6];
    const float* Wo = (const float*)d_in[7];
    const float* bo = (const float*)d_in[8];
    float* out = (float*)d_out;

    __nv_bfloat16 *xhi, *xlo, *ahi, *alo, *qhh, *qll, *khh, *kll, *vhh, *vll;
    __nv_bfloat16 *wqh, *wql, *wkh, *wkl, *wvh, *wvl, *woh, *wol;
    cudaGetSymbolAddress((void**)&xhi, g_xhi);
    cudaGetSymbolAddress((void**)&xlo, g_xlo);
    cudaGetSymbolAddress((void**)&ahi, g_ahi);
    cudaGetSymbolAddress((void**)&alo, g_alo);
    cudaGetSymbolAddress((void**)&qhh, g_qh);
    cudaGetSymbolAddress((void**)&qll, g_ql);
    cudaGetSymbolAddress((void**)&khh, g_kh);
    cudaGetSymbolAddress((void**)&kll, g_kl);
    cudaGetSymbolAddress((void**)&vhh, g_vh);
    cudaGetSymbolAddress((void**)&vll, g_vl);
    cudaGetSymbolAddress((void**)&wqh, g_wq_hi);
    cudaGetSymbolAddress((void**)&wql, g_wq_lo);
    cudaGetSymbolAddress((void**)&wkh, g_wk_hi);
    cudaGetSymbolAddress((void**)&wkl, g_wk_lo);
    cudaGetSymbolAddress((void**)&wvh, g_wv_hi);
    cudaGetSymbolAddress((void**)&wvl, g_wv_lo);
    cudaGetSymbolAddress((void**)&woh, g_wo_hi);
    cudaGetSymbolAddress((void**)&wol, g_wo_lo);

    cudaFuncSetAttribute(gemm_qkv, cudaFuncAttributeMaxDynamicSharedMemorySize, GEMM_SMEM);
    cudaFuncSetAttribute(gemm_bf16x2, cudaFuncAttributeMaxDynamicSharedMemorySize, GEMM_SMEM);
    cudaFuncSetAttribute(flash_attn_mma, cudaFuncAttributeMaxDynamicSharedMemorySize, ATT_SMEM);

    // prep: split x, transpose+split weights
    int n4x = ROWS * DMODEL / 4;
    split_kernel<<<(n4x + 255) / 256, 256>>>((const float4*)x, xhi, xlo, n4x);
    dim3 tgrid(DMODEL / 32, DMODEL / 32);
    transpose_split<<<tgrid, 256>>>(Wq, wqh, wql);
    transpose_split<<<tgrid, 256>>>(Wk, wkh, wkl);
    transpose_split<<<tgrid, 256>>>(Wv, wvh, wvl);
    transpose_split<<<tgrid, 256>>>(Wo, woh, wol);

    // fused QKV projection + rotary + split
    dim3 qkv_grid(3 * DMODEL / TN, ROWS / TM);   // (48, 32)
    gemm_qkv<<<qkv_grid, 256, GEMM_SMEM>>>(xhi, xlo, wqh, wql, wkh, wkl, wvh, wvl,
                                           bq, bk, bv, qhh, qll, khh, kll, vhh, vll);

    // tensor-core flash attention (emits bf16 hi/lo)
    dim3 attn_grid(NSEQ / 64, BATCH * HEADS);   // (32, 32)
    flash_attn_mma<<<attn_grid, 128, ATT_SMEM>>>(qhh, qll, khh, kll, vhh, vll, ahi, alo);

    // output projection
    dim3 ggrid(DMODEL / TN, ROWS / TM);   // (16, 32)
    gemm_bf16x2<<<ggrid, 256, GEMM_SMEM>>>(ahi, alo, woh, wol, bo, out);
}